// round 14
// baseline (speedup 1.0000x reference)
#include <cuda_runtime.h>
#include <cuda_fp16.h>
#include <mma.h>
#include <math.h>

using namespace nvcuda;

// ---------------- problem constants ----------------
#define BB 64
#define SS 168
#define F_IN 10
#define DD 512
#define HH 8
#define LL 4
#define HID 2048
#define NFUT 48
#define DH (DD*HH)          // 4096
#define QKVN (3*DH)         // 12288
#define MTOK (BB*SS)        // 10752

// ---------------- scratch ----------------
__device__ __half g_h   [MTOK*DD];
__device__ __half g_h1  [MTOK*DD];
__device__ float  g_t   [MTOK*DD];
__device__ __half g_qkv [MTOK*QKVN];
__device__ __half g_ctx [MTOK*DH];
__device__ float  g_s   [BB*HH*SS*SS];
__device__ __half g_p   [BB*HH*SS*SS];
__device__ __half g_mlp [MTOK*HID];
__device__ __half g_wqkv[LL*DD*QKVN];
__device__ float  g_bqkv[LL*QKVN];
__device__ __half g_wd  [LL*DH*DD];
__device__ __half g_wmh [LL*DD*HID];
__device__ __half g_wmo [LL*HID*DD];

// ---------------- cp.async helpers ----------------
__device__ __forceinline__ void cp16(void* dst, const void* src, int bytes) {
    unsigned d = (unsigned)__cvta_generic_to_shared(dst);
    asm volatile("cp.async.cg.shared.global [%0], [%1], 16, %2;\n"
                 :: "r"(d), "l"(src), "r"(bytes));
}
__device__ __forceinline__ void cp16f(void* dst, const void* src) {
    unsigned d = (unsigned)__cvta_generic_to_shared(dst);
    asm volatile("cp.async.cg.shared.global [%0], [%1], 16;\n"
                 :: "r"(d), "l"(src));
}
__device__ __forceinline__ void cp_commit() {
    asm volatile("cp.async.commit_group;\n" ::: "memory");
}
__device__ __forceinline__ void cp_wait1() {
    asm volatile("cp.async.wait_group 1;\n" ::: "memory");
}
__device__ __forceinline__ void cp_wait0() {
    asm volatile("cp.async.wait_group 0;\n" ::: "memory");
}

// smem size needed per config (stage buffers vs whole-tile epilogue)
template<int TMT, int TNT, bool TRB>
struct SmemNeed {
    static constexpr int LDA = 72;
    static constexpr int A_T = TMT * LDA;
    static constexpr int B_T = TRB ? (TNT * LDA) : (64 * (TNT + 8));
    static constexpr int STAGE2 = 2 * ((A_T + B_T) * 2);
    static constexpr int EPI = TMT * (TNT + 4) * 4;
    static constexpr int BYTES = STAGE2 > EPI ? STAGE2 : EPI;
};

// ================= templated fp16 GEMM (2-stage mainloop + coalesced epilogue) ========
// C = alpha * A[M,K] @ (TRB ? B^T : B) (+bias) (+relu); OUTH: half out else fp32.
// CAUSAL: 0 = none; 1 = skip tiles fully above diagonal (scores);
//         2 = truncate K at tile_m+TMT (PV over causal probs; exact, probs==0 there).
template<int TMT, int TNT, int NWM, int NWN, int MINB, int CAUSAL,
         bool TRB, bool BIAS, bool RELU, bool OUTH>
__global__ void __launch_bounds__(NWM*NWN*32, MINB)
gemm_h(const __half* __restrict__ A, const __half* __restrict__ Bm,
       const float* __restrict__ bias, float* __restrict__ Cf, __half* __restrict__ Ch,
       int M, int N, int K, int lda, int ldb, int ldc,
       long long sAb, long long sAh, long long sBb, long long sBh,
       long long sCb, long long sCh, int Hs, float alpha)
{
    constexpr int THREADS = NWM * NWN * 32;
    constexpr int TKc = 64;
    constexpr int LDA = TKc + 8;                 // 72 halves (144B, 16B-mult)
    constexpr int LDB = TNT + 8;
    constexpr int A_T = TMT * LDA;               // halves
    constexpr int B_T = TRB ? (TNT * LDA) : (TKc * LDB);
    constexpr int STAGE = (A_T + B_T) * 2;       // bytes
    constexpr int WROWS = TMT / NWM, WCOLS = TNT / NWN;
    constexpr int FM = WROWS / 16, FN = WCOLS / 16;
    constexpr int JA = TMT * (TKc / 8) / THREADS;
    constexpr int JB = (TRB ? TNT * (TKc / 8) : TKc * (TNT / 8)) / THREADS;

    extern __shared__ char smraw[];

    const int tile_m = blockIdx.y * TMT;
    const int tile_n = blockIdx.x * TNT;

    if (CAUSAL == 1 && tile_n >= tile_m + TMT) return;
    const int Kp = (CAUSAL == 2) ? min(K, tile_m + TMT) : K;

    const int z = blockIdx.z;
    const int b = z / Hs, hh = z % Hs;
    A  += (long long)b * sAb + (long long)hh * sAh;
    Bm += (long long)b * sBb + (long long)hh * sBh;
    if (OUTH) Ch += (long long)b * sCb + (long long)hh * sCh;
    else      Cf += (long long)b * sCb + (long long)hh * sCh;

    const int tid  = threadIdx.x;
    const int warp = tid >> 5;
    const int wm = warp % NWM;
    const int wn = warp / NWM;

    wmma::fragment<wmma::accumulator, 16, 16, 16, float> cf[FM][FN];
    #pragma unroll
    for (int i = 0; i < FM; i++)
        #pragma unroll
        for (int j = 0; j < FN; j++)
            wmma::fill_fragment(cf[i][j], 0.0f);

    const int nIter = (Kp + TKc - 1) / TKc;
    const bool full = (tile_m + TMT <= M) && (tile_n + TNT <= N);
    const bool fast = full && ((Kp & (TKc - 1)) == 0);

    auto compute = [&](int bufi) {
        const __half* sA = (const __half*)(smraw + bufi * STAGE);
        const __half* sB = sA + A_T;
        #pragma unroll
        for (int kk = 0; kk < TKc; kk += 16) {
            wmma::fragment<wmma::matrix_a, 16, 16, 16, __half, wmma::row_major> af[FM];
            #pragma unroll
            for (int mi = 0; mi < FM; mi++)
                wmma::load_matrix_sync(af[mi], sA + (wm * WROWS + mi * 16) * LDA + kk, LDA);
            if (!TRB) {
                wmma::fragment<wmma::matrix_b, 16, 16, 16, __half, wmma::row_major> bf[FN];
                #pragma unroll
                for (int ni = 0; ni < FN; ni++)
                    wmma::load_matrix_sync(bf[ni], sB + kk * LDB + (wn * WCOLS + ni * 16), LDB);
                #pragma unroll
                for (int mi = 0; mi < FM; mi++)
                    #pragma unroll
                    for (int ni = 0; ni < FN; ni++)
                        wmma::mma_sync(cf[mi][ni], af[mi], bf[ni], cf[mi][ni]);
            } else {
                wmma::fragment<wmma::matrix_b, 16, 16, 16, __half, wmma::col_major> bf[FN];
                #pragma unroll
                for (int ni = 0; ni < FN; ni++)
                    wmma::load_matrix_sync(bf[ni], sB + (wn * WCOLS + ni * 16) * LDA + kk, LDA);
                #pragma unroll
                for (int mi = 0; mi < FM; mi++)
                    #pragma unroll
                    for (int ni = 0; ni < FN; ni++)
                        wmma::mma_sync(cf[mi][ni], af[mi], bf[ni], cf[mi][ni]);
            }
        }
    };

    if (fast) {
        int dA[JA]; const __half* pA[JA];
        int dB[JB]; const __half* pB[JB];
        long long stepB;
        #pragma unroll
        for (int j = 0; j < JA; j++) {
            int c = tid + j * THREADS;
            int r = c >> 3, kc = (c & 7) * 8;
            dA[j] = (r * LDA + kc) * 2;
            pA[j] = A + (long long)(tile_m + r) * lda + kc;
        }
        if (!TRB) {
            #pragma unroll
            for (int j = 0; j < JB; j++) {
                int c = tid + j * THREADS;
                int r = c / (TNT / 8), nc = (c % (TNT / 8)) * 8;
                dB[j] = (A_T + r * LDB + nc) * 2;
                pB[j] = Bm + (long long)r * ldb + tile_n + nc;
            }
            stepB = (long long)TKc * ldb;
        } else {
            #pragma unroll
            for (int j = 0; j < JB; j++) {
                int c = tid + j * THREADS;
                int r = c >> 3, kc = (c & 7) * 8;
                dB[j] = (A_T + r * LDA + kc) * 2;
                pB[j] = Bm + (long long)(tile_n + r) * ldb + kc;
            }
            stepB = TKc;
        }
        auto stageF = [&](int bufi) {
            char* base = smraw + bufi * STAGE;
            #pragma unroll
            for (int j = 0; j < JA; j++) { cp16f(base + dA[j], pA[j]); pA[j] += TKc; }
            #pragma unroll
            for (int j = 0; j < JB; j++) { cp16f(base + dB[j], pB[j]); pB[j] += stepB; }
        };
        stageF(0);
        cp_commit();
        int buf = 0;
        for (int it = 0; it < nIter; ++it) {
            if (it + 1 < nIter) { stageF(buf ^ 1); cp_commit(); cp_wait1(); }
            else cp_wait0();
            __syncthreads();
            compute(buf);
            __syncthreads();
            buf ^= 1;
        }
    } else {
        auto stageS = [&](int it, int bufi) {
            const int k0 = it * TKc;
            __half* sA = (__half*)(smraw + bufi * STAGE);
            __half* sB = sA + A_T;
            #pragma unroll
            for (int j = 0; j < JA; j++) {
                int c = tid + j * THREADS;
                int r = c >> 3, kc = (c & 7) * 8;
                int gm = tile_m + r, gk = k0 + kc;
                int bytes = (gm < M && gk + 8 <= Kp) ? 16 : 0;
                const __half* src = bytes ? (A + (long long)gm * lda + gk) : A;
                cp16(sA + r * LDA + kc, src, bytes);
            }
            if (!TRB) {
                #pragma unroll
                for (int j = 0; j < JB; j++) {
                    int c = tid + j * THREADS;
                    int r = c / (TNT / 8), nc = (c % (TNT / 8)) * 8;
                    int gk = k0 + r, gn = tile_n + nc;
                    int bytes = (gk < Kp && gn + 8 <= N) ? 16 : 0;
                    const __half* src = bytes ? (Bm + (long long)gk * ldb + gn) : Bm;
                    cp16(sB + r * LDB + nc, src, bytes);
                }
            } else {
                #pragma unroll
                for (int j = 0; j < JB; j++) {
                    int c = tid + j * THREADS;
                    int r = c >> 3, kc = (c & 7) * 8;
                    int gn = tile_n + r, gk = k0 + kc;
                    int bytes = (gn < N && gk + 8 <= Kp) ? 16 : 0;
                    const __half* src = bytes ? (Bm + (long long)gn * ldb + gk) : Bm;
                    cp16(sB + r * LDA + kc, src, bytes);
                }
            }
        };
        stageS(0, 0);
        cp_commit();
        int buf = 0;
        for (int it = 0; it < nIter; ++it) {
            if (it + 1 < nIter) { stageS(it + 1, buf ^ 1); cp_commit(); cp_wait1(); }
            else cp_wait0();
            __syncthreads();
            compute(buf);
            __syncthreads();
            buf ^= 1;
        }
    }

    // ---- epilogue: whole-tile smem staging + coalesced vector writeback ----
    __syncthreads();   // mainloop done; stage buffers free for reuse

    constexpr int LDC_S = TNT + 4;               // floats; mult of 4 (16B) for wmma
    float* tileS = (float*)smraw;

    #pragma unroll
    for (int mi = 0; mi < FM; mi++)
        #pragma unroll
        for (int ni = 0; ni < FN; ni++)
            wmma::store_matrix_sync(tileS + (wm * WROWS + mi * 16) * LDC_S
                                          + (wn * WCOLS + ni * 16),
                                    cf[mi][ni], LDC_S, wmma::mem_row_major);
    __syncthreads();

    constexpr int CH = TMT * TNT / 4 / THREADS;  // float4 chunks per thread
    #pragma unroll
    for (int j = 0; j < CH; j++) {
        int c = tid + j * THREADS;
        int rr = c / (TNT / 4);
        int cc = (c % (TNT / 4)) * 4;
        int gm = tile_m + rr;
        int gn = tile_n + cc;
        float4 v = *reinterpret_cast<const float4*>(tileS + rr * LDC_S + cc);
        v.x *= alpha; v.y *= alpha; v.z *= alpha; v.w *= alpha;
        if (BIAS) {
            float4 bv = *reinterpret_cast<const float4*>(bias + gn);
            v.x += bv.x; v.y += bv.y; v.z += bv.z; v.w += bv.w;
        }
        if (RELU) {
            v.x = fmaxf(v.x, 0.0f); v.y = fmaxf(v.y, 0.0f);
            v.z = fmaxf(v.z, 0.0f); v.w = fmaxf(v.w, 0.0f);
        }
        if (full) {
            if (OUTH) {
                __half2 h01 = __floats2half2_rn(v.x, v.y);
                __half2 h23 = __floats2half2_rn(v.z, v.w);
                uint2 pk = make_uint2(*(unsigned*)&h01, *(unsigned*)&h23);
                *reinterpret_cast<uint2*>(Ch + (long long)gm * ldc + gn) = pk;
            } else {
                *reinterpret_cast<float4*>(Cf + (long long)gm * ldc + gn) = v;
            }
        } else if (gm < M) {
            float e[4] = { v.x, v.y, v.z, v.w };
            #pragma unroll
            for (int q = 0; q < 4; q++) {
                if (gn + q < N) {
                    if (OUTH) Ch[(long long)gm * ldc + gn + q] = __float2half_rn(e[q]);
                    else      Cf[(long long)gm * ldc + gn + q] = e[q];
                }
            }
        }
    }
}

template<int TMT, int TNT, int NWM, int NWN, int MINB, int CAUSAL,
         bool TRB, bool BIAS, bool RELU, bool OUTH>
static inline void run_gemm(const __half* A, const __half* B, const float* bias,
                            float* Cf, __half* Ch,
                            int M, int N, int K, int lda, int ldb, int ldc,
                            long long sAb, long long sAh, long long sBb, long long sBh,
                            long long sCb, long long sCh, int Hs, int Z, float alpha)
{
    constexpr int SMEM = SmemNeed<TMT, TNT, TRB>::BYTES;
    static bool s_init = false;
    if (!s_init) {
        cudaFuncSetAttribute(gemm_h<TMT,TNT,NWM,NWN,MINB,CAUSAL,TRB,BIAS,RELU,OUTH>,
                             cudaFuncAttributeMaxDynamicSharedMemorySize, SMEM);
        s_init = true;
    }
    dim3 grid((N + TNT - 1) / TNT, (M + TMT - 1) / TMT, Z);
    gemm_h<TMT,TNT,NWM,NWN,MINB,CAUSAL,TRB,BIAS,RELU,OUTH><<<grid, NWM*NWN*32, SMEM>>>(
        A, B, bias, Cf, Ch, M, N, K, lda, ldb, ldc,
        sAb, sAh, sBb, sBh, sCb, sCh, Hs, alpha);
}

// ---------------- weight conversion ----------------
__global__ void f2h_kernel(const float4* __restrict__ in, __half2* __restrict__ out, int n4)
{
    int i = blockIdx.x * 256 + threadIdx.x;
    if (i >= n4) return;
    float4 v = in[i];
    out[2 * i]     = __floats2half2_rn(v.x, v.y);
    out[2 * i + 1] = __floats2half2_rn(v.z, v.w);
}

__global__ void f2h_off(const float* __restrict__ src, __half* __restrict__ dst, int off)
{
    long long i = (long long)blockIdx.x * 256 + threadIdx.x;
    const long long tot = (long long)LL * DD * (DH / 2);
    if (i >= tot) return;
    int z   = (int)(i / (DD * (DH / 2)));
    int rem = (int)(i % (DD * (DH / 2)));
    int k = rem / (DH / 2), n2 = rem % (DH / 2);
    float2 v = *(const float2*)(src + (long long)z * DD * DH + (long long)k * DH + n2 * 2);
    *(__half2*)(dst + (long long)z * DD * QKVN + (long long)k * QKVN + off + n2 * 2)
        = __floats2half2_rn(v.x, v.y);
}

__global__ void bias_concat(const float* __restrict__ q, const float* __restrict__ k,
                            const float* __restrict__ v, float* __restrict__ o)
{
    int i = blockIdx.x * 256 + threadIdx.x;
    if (i >= LL * QKVN) return;
    int z = i / QKVN, c = i % QKVN;
    float val = (c < DH) ? q[z * DH + c]
              : (c < 2 * DH) ? k[z * DH + c - DH]
              : v[z * DH + c - 2 * DH];
    o[i] = val;
}

// ---------------- embedding (half out) ----------------
__global__ void embed_kernel(const float* __restrict__ x, const float* __restrict__ w,
                             const float* __restrict__ b, __half* __restrict__ h)
{
    int idx = blockIdx.x * 256 + threadIdx.x;
    if (idx >= MTOK * DD) return;
    int row = idx / DD, d = idx % DD;
    int s = row % SS;
    const float* xr = x + row * F_IN;
    float acc = b[d];
    #pragma unroll
    for (int f = 0; f < F_IN; f++) acc += xr[f] * w[f * DD + d];
    acc *= 22.627416997969522f;
    float di2 = (float)(2 * (d >> 1));
    float ang = (float)s * expf(di2 * (-9.210340371976184f / (float)DD));
    float pe = (d & 1) ? cosf(ang) : sinf(ang);
    h[idx] = __float2half_rn(acc + pe);
}

// ---------------- causal softmax: fp32 scores -> half probs ----------------
__global__ void softmax_kernel(const float* __restrict__ s, __half* __restrict__ pr)
{
    int row = blockIdx.x * 8 + (threadIdx.x >> 5);
    if (row >= BB * HH * SS) return;
    int lane = threadIdx.x & 31;
    int q = row % SS;
    const float* p = s + (long long)row * SS;
    __half* o = pr + (long long)row * SS;

    float m = -1e30f;
    for (int j = lane; j <= q; j += 32) m = fmaxf(m, p[j]);
    #pragma unroll
    for (int off = 16; off; off >>= 1) m = fmaxf(m, __shfl_xor_sync(0xffffffffu, m, off));

    float sum = 0.0f;
    for (int j = lane; j <= q; j += 32) sum += expf(p[j] - m);
    #pragma unroll
    for (int off = 16; off; off >>= 1) sum += __shfl_xor_sync(0xffffffffu, sum, off);
    float inv = 1.0f / sum;

    for (int j = lane; j < SS; j += 32)
        o[j] = (j <= q) ? __float2half_rn(expf(p[j] - m) * inv) : __float2half_rn(0.0f);
}

// ---------------- fused residual-add + LayerNorm ----------------
__global__ void add_ln_kernel(const float* __restrict__ a, const __half* __restrict__ r,
                              const float* __restrict__ g, const float* __restrict__ bt,
                              __half* __restrict__ o)
{
    int row = blockIdx.x;
    int t = threadIdx.x;
    long long base = (long long)row * DD;
    float x0 = a[base + t]       + __half2float(r[base + t]);
    float x1 = a[base + t + 256] + __half2float(r[base + t + 256]);
    float sm = x0 + x1, sq = x0 * x0 + x1 * x1;
    #pragma unroll
    for (int off = 16; off; off >>= 1) {
        sm += __shfl_xor_sync(0xffffffffu, sm, off);
        sq += __shfl_xor_sync(0xffffffffu, sq, off);
    }
    __shared__ float sh[2][8];
    if ((t & 31) == 0) { sh[0][t >> 5] = sm; sh[1][t >> 5] = sq; }
    __syncthreads();
    float S = 0, Q = 0;
    #pragma unroll
    for (int j = 0; j < 8; j++) { S += sh[0][j]; Q += sh[1][j]; }
    float mean = S * (1.0f / DD);
    float var  = Q * (1.0f / DD) - mean * mean;
    float inv  = rsqrtf(var + 1e-9f);
    o[base + t]       = __float2half_rn((x0 - mean) * inv * g[t]       + bt[t]);
    o[base + t + 256] = __float2half_rn((x1 - mean) * inv * g[t + 256] + bt[t + 256]);
}

// ---------------- final projection ----------------
__global__ void out_kernel(const __half* __restrict__ h, const float* __restrict__ w,
                           const float* __restrict__ b, float* __restrict__ out)
{
    int r = blockIdx.x * 4 + (threadIdx.x >> 5);
    if (r >= BB * NFUT) return;
    int lane = threadIdx.x & 31;
    int bb = r / NFUT, si = r % NFUT;
    const __half* hr = h + ((long long)bb * SS + (SS - NFUT) + si) * DD;
    float acc = 0.0f;
    for (int d = lane; d < DD; d += 32) acc += __half2float(hr[d]) * w[d];
    #pragma unroll
    for (int o = 16; o; o >>= 1) acc += __shfl_xor_sync(0xffffffffu, acc, o);
    if (lane == 0) out[r] = acc + b[0];
}

extern "C" void kernel_launch(void* const* d_in, const int* in_sizes, int n_in,
                              void* d_out, int out_size)
{
    const float* x    = (const float*)d_in[0];
    const float* in_w = (const float*)d_in[2];
    const float* in_b = (const float*)d_in[3];
    const float* wq_w = (const float*)d_in[4];
    const float* wq_b = (const float*)d_in[5];
    const float* wk_w = (const float*)d_in[6];
    const float* wk_b = (const float*)d_in[7];
    const float* wv_w = (const float*)d_in[8];
    const float* wv_b = (const float*)d_in[9];
    const float* dn_w = (const float*)d_in[10];
    const float* dn_b = (const float*)d_in[11];
    const float* mh_w = (const float*)d_in[12];
    const float* mh_b = (const float*)d_in[13];
    const float* mo_w = (const float*)d_in[14];
    const float* mo_b = (const float*)d_in[15];
    const float* ln1g = (const float*)d_in[16];
    const float* ln1b = (const float*)d_in[17];
    const float* ln3g = (const float*)d_in[18];
    const float* ln3b = (const float*)d_in[19];
    const float* ow   = (const float*)d_in[20];
    const float* ob   = (const float*)d_in[21];

    __half *h, *h1, *qkv, *ctx, *p, *mlp;
    float *t, *sc, *bqkv;
    __half *wqkvh, *wdh, *wmhh, *wmoh;
    cudaGetSymbolAddress((void**)&h,     g_h);
    cudaGetSymbolAddress((void**)&h1,    g_h1);
    cudaGetSymbolAddress((void**)&t,     g_t);
    cudaGetSymbolAddress((void**)&qkv,   g_qkv);
    cudaGetSymbolAddress((void**)&ctx,   g_ctx);
    cudaGetSymbolAddress((void**)&sc,    g_s);
    cudaGetSymbolAddress((void**)&p,     g_p);
    cudaGetSymbolAddress((void**)&mlp,   g_mlp);
    cudaGetSymbolAddress((void**)&wqkvh, g_wqkv);
    cudaGetSymbolAddress((void**)&bqkv,  g_bqkv);
    cudaGetSymbolAddress((void**)&wdh,   g_wd);
    cudaGetSymbolAddress((void**)&wmhh,  g_wmh);
    cudaGetSymbolAddress((void**)&wmoh,  g_wmo);

    // weight conversion (once per call; graph-capturable)
    {
        const long long totq = (long long)LL * DD * (DH / 2);
        const int gq = (int)((totq + 255) / 256);
        f2h_off<<<gq, 256>>>(wq_w, wqkvh, 0);
        f2h_off<<<gq, 256>>>(wk_w, wqkvh, DH);
        f2h_off<<<gq, 256>>>(wv_w, wqkvh, 2 * DH);
        bias_concat<<<(LL * QKVN + 255) / 256, 256>>>(wq_b, wk_b, wv_b, bqkv);
        const int n_qkv = LL * DD * DH / 4;
        const int n_mlp = LL * DD * HID / 4;
        f2h_kernel<<<(n_qkv + 255) / 256, 256>>>((const float4*)dn_w, (__half2*)wdh,  n_qkv);
        f2h_kernel<<<(n_mlp + 255) / 256, 256>>>((const float4*)mh_w, (__half2*)wmhh, n_mlp);
        f2h_kernel<<<(n_mlp + 255) / 256, 256>>>((const float4*)mo_w, (__half2*)wmoh, n_mlp);
    }

    const float inv_sqrt_d = 0.044194173824159216f;

    embed_kernel<<<(MTOK * DD + 255) / 256, 256>>>(x, in_w, in_b, h);

    for (int i = 0; i < LL; i++) {
        // fused QKV: [10752,512] @ [512,12288] — 256x128 tile, 512 threads (16 warps)
        run_gemm<256,128,4,4,1, 0, false,true,false,true>(
            h, wqkvh + (long long)i * DD * QKVN, bqkv + (long long)i * QKVN, nullptr, qkv,
            MTOK, QKVN, DD, DD, QKVN, QKVN, 0,0,0,0,0,0, 1, 1, 1.0f);

        // scores = Q @ K^T * inv_sqrt_d (small tile, TRB, fp32 out, causal tile-skip)
        run_gemm<64,64,2,2,4, 1, true,false,false,false>(
            qkv, qkv + DH, nullptr, sc, nullptr,
            SS, SS, DD, QKVN, QKVN, SS,
            (long long)SS * QKVN, DD,
            (long long)SS * QKVN, DD,
            (long long)HH * SS * SS, (long long)SS * SS,
            HH, BB * HH, inv_sqrt_d);

        softmax_kernel<<<(BB * HH * SS + 7) / 8, 256>>>(sc, p);

        // context = P @ V (small tile, half out, causal K-truncation)
        run_gemm<64,64,2,2,4, 2, false,false,false,true>(
            p, qkv + 2 * DH, nullptr, nullptr, ctx,
            SS, DD, SS, SS, QKVN, DH,
            (long long)HH * SS * SS, (long long)SS * SS,
            (long long)SS * QKVN, DD,
            (long long)SS * DH, DD,
            HH, BB * HH, 1.0f);

        // dn (small tile, fp32 out -> LN)
        run_gemm<64,64,2,2,4, 0, false,true,false,false>(
            ctx, wdh + (long long)i * DH * DD, dn_b + (long long)i * DD, t, nullptr,
            MTOK, DD, DH, DH, DD, DD, 0,0,0,0,0,0, 1, 1, 1.0f);

        add_ln_kernel<<<MTOK, 256>>>(t, h, ln1g + (long long)i * DD, ln1b + (long long)i * DD, h1);

        // MLP up — 256x128 tile, 512 threads, relu, half out
        run_gemm<256,128,4,4,1, 0, false,true,true,true>(
            h1, wmhh + (long long)i * DD * HID, mh_b + (long long)i * HID, nullptr, mlp,
            MTOK, HID, DD, DD, HID, HID, 0,0,0,0,0,0, 1, 1, 1.0f);

        // MLP down (small tile, fp32 out -> LN)
        run_gemm<64,64,2,2,4, 0, false,true,false,false>(
            mlp, wmoh + (long long)i * HID * DD, mo_b + (long long)i * DD, t, nullptr,
            MTOK, DD, HID, HID, DD, DD, 0,0,0,0,0,0, 1, 1, 1.0f);

        add_ln_kernel<<<MTOK, 256>>>(t, h1, ln3g + (long long)i * DD, ln3b + (long long)i * DD, h);
    }

    out_kernel<<<(BB * NFUT + 3) / 4, 128>>>(h, ow, ob, (float*)d_out);
}

// round 15
// speedup vs baseline: 1.0847x; 1.0847x over previous
#include <cuda_runtime.h>
#include <cuda_fp16.h>
#include <mma.h>
#include <math.h>

using namespace nvcuda;

// ---------------- problem constants ----------------
#define BB 64
#define SS 168
#define F_IN 10
#define DD 512
#define HH 8
#define LL 4
#define HID 2048
#define NFUT 48
#define DH (DD*HH)          // 4096
#define MTOK (BB*SS)        // 10752

// ---------------- scratch ----------------
__device__ __half g_h   [MTOK*DD];
__device__ __half g_h1  [MTOK*DD];
__device__ float  g_t   [MTOK*DD];
__device__ __half g_qkv [3LL*MTOK*DH];     // [3][MTOK][DH] planes: Q,K,V
__device__ __half g_ctx [MTOK*DH];
__device__ float  g_s   [BB*HH*SS*SS];
__device__ __half g_p   [BB*HH*SS*SS];
__device__ __half g_mlp [MTOK*HID];
__device__ __half g_wqkv[3LL*LL*DD*DH];    // [3][LL][DD*DH] contiguous
__device__ float  g_bqkv[3LL*LL*DH];       // [3][LL][DH]
__device__ __half g_wd  [LL*DH*DD];
__device__ __half g_wmh [LL*DD*HID];
__device__ __half g_wmo [LL*HID*DD];

// ---------------- cp.async helpers ----------------
__device__ __forceinline__ void cp16(void* dst, const void* src, int bytes) {
    unsigned d = (unsigned)__cvta_generic_to_shared(dst);
    asm volatile("cp.async.cg.shared.global [%0], [%1], 16, %2;\n"
                 :: "r"(d), "l"(src), "r"(bytes));
}
__device__ __forceinline__ void cp16f(void* dst, const void* src) {
    unsigned d = (unsigned)__cvta_generic_to_shared(dst);
    asm volatile("cp.async.cg.shared.global [%0], [%1], 16;\n"
                 :: "r"(d), "l"(src));
}
__device__ __forceinline__ void cp_commit() {
    asm volatile("cp.async.commit_group;\n" ::: "memory");
}
__device__ __forceinline__ void cp_wait1() {
    asm volatile("cp.async.wait_group 1;\n" ::: "memory");
}
__device__ __forceinline__ void cp_wait0() {
    asm volatile("cp.async.wait_group 0;\n" ::: "memory");
}

// smem size needed per config (stage buffers vs whole-tile epilogue)
template<int TMT, int TNT, bool TRB>
struct SmemNeed {
    static constexpr int LDA = 72;
    static constexpr int A_T = TMT * LDA;
    static constexpr int B_T = TRB ? (TNT * LDA) : (64 * (TNT + 8));
    static constexpr int STAGE2 = 2 * ((A_T + B_T) * 2);
    static constexpr int EPI = TMT * (TNT + 4) * 4;
    static constexpr int BYTES = STAGE2 > EPI ? STAGE2 : EPI;
};

// ================= templated fp16 GEMM (R13 mainloop + coalesced epilogue) ============
// C = alpha * A[M,K] @ (TRB ? B^T : B) (+bias[+hh*sBib]) (+relu); OUTH: half out.
// CAUSAL: 0 = none; 1 = skip tiles fully above diagonal (scores);
//         2 = truncate K at tile_m+TMT (PV over causal probs; exact, probs==0 there).
template<int TMT, int TNT, int NWM, int NWN, int MINB, int CAUSAL,
         bool TRB, bool BIAS, bool RELU, bool OUTH>
__global__ void __launch_bounds__(NWM*NWN*32, MINB)
gemm_h(const __half* __restrict__ A, const __half* __restrict__ Bm,
       const float* __restrict__ bias, float* __restrict__ Cf, __half* __restrict__ Ch,
       int M, int N, int K, int lda, int ldb, int ldc,
       long long sAb, long long sAh, long long sBb, long long sBh,
       long long sCb, long long sCh, long long sBib, int Hs, float alpha)
{
    constexpr int THREADS = NWM * NWN * 32;
    constexpr int TKc = 64;
    constexpr int LDA = TKc + 8;                 // 72 halves (144B, 16B-mult)
    constexpr int LDB = TNT + 8;
    constexpr int A_T = TMT * LDA;               // halves
    constexpr int B_T = TRB ? (TNT * LDA) : (TKc * LDB);
    constexpr int STAGE = (A_T + B_T) * 2;       // bytes
    constexpr int WROWS = TMT / NWM, WCOLS = TNT / NWN;
    constexpr int FM = WROWS / 16, FN = WCOLS / 16;
    constexpr int JA = TMT * (TKc / 8) / THREADS;
    constexpr int JB = (TRB ? TNT * (TKc / 8) : TKc * (TNT / 8)) / THREADS;

    extern __shared__ char smraw[];

    const int tile_m = blockIdx.y * TMT;
    const int tile_n = blockIdx.x * TNT;

    if (CAUSAL == 1 && tile_n >= tile_m + TMT) return;
    const int Kp = (CAUSAL == 2) ? min(K, tile_m + TMT) : K;

    const int z = blockIdx.z;
    const int b = z / Hs, hh = z % Hs;
    A  += (long long)b * sAb + (long long)hh * sAh;
    Bm += (long long)b * sBb + (long long)hh * sBh;
    if (BIAS) bias += (long long)hh * sBib;
    if (OUTH) Ch += (long long)b * sCb + (long long)hh * sCh;
    else      Cf += (long long)b * sCb + (long long)hh * sCh;

    const int tid  = threadIdx.x;
    const int warp = tid >> 5;
    const int wm = warp % NWM;
    const int wn = warp / NWM;

    wmma::fragment<wmma::accumulator, 16, 16, 16, float> cf[FM][FN];
    #pragma unroll
    for (int i = 0; i < FM; i++)
        #pragma unroll
        for (int j = 0; j < FN; j++)
            wmma::fill_fragment(cf[i][j], 0.0f);

    const int nIter = (Kp + TKc - 1) / TKc;
    const bool full = (tile_m + TMT <= M) && (tile_n + TNT <= N);
    const bool fast = full && ((Kp & (TKc - 1)) == 0);

    auto compute = [&](int bufi) {
        const __half* sA = (const __half*)(smraw + bufi * STAGE);
        const __half* sB = sA + A_T;
        #pragma unroll
        for (int kk = 0; kk < TKc; kk += 16) {
            wmma::fragment<wmma::matrix_a, 16, 16, 16, __half, wmma::row_major> af[FM];
            #pragma unroll
            for (int mi = 0; mi < FM; mi++)
                wmma::load_matrix_sync(af[mi], sA + (wm * WROWS + mi * 16) * LDA + kk, LDA);
            if (!TRB) {
                wmma::fragment<wmma::matrix_b, 16, 16, 16, __half, wmma::row_major> bf[FN];
                #pragma unroll
                for (int ni = 0; ni < FN; ni++)
                    wmma::load_matrix_sync(bf[ni], sB + kk * LDB + (wn * WCOLS + ni * 16), LDB);
                #pragma unroll
                for (int mi = 0; mi < FM; mi++)
                    #pragma unroll
                    for (int ni = 0; ni < FN; ni++)
                        wmma::mma_sync(cf[mi][ni], af[mi], bf[ni], cf[mi][ni]);
            } else {
                wmma::fragment<wmma::matrix_b, 16, 16, 16, __half, wmma::col_major> bf[FN];
                #pragma unroll
                for (int ni = 0; ni < FN; ni++)
                    wmma::load_matrix_sync(bf[ni], sB + (wn * WCOLS + ni * 16) * LDA + kk, LDA);
                #pragma unroll
                for (int mi = 0; mi < FM; mi++)
                    #pragma unroll
                    for (int ni = 0; ni < FN; ni++)
                        wmma::mma_sync(cf[mi][ni], af[mi], bf[ni], cf[mi][ni]);
            }
        }
    };

    if (fast) {
        int dA[JA]; const __half* pA[JA];
        int dB[JB]; const __half* pB[JB];
        long long stepB;
        #pragma unroll
        for (int j = 0; j < JA; j++) {
            int c = tid + j * THREADS;
            int r = c >> 3, kc = (c & 7) * 8;
            dA[j] = (r * LDA + kc) * 2;
            pA[j] = A + (long long)(tile_m + r) * lda + kc;
        }
        if (!TRB) {
            #pragma unroll
            for (int j = 0; j < JB; j++) {
                int c = tid + j * THREADS;
                int r = c / (TNT / 8), nc = (c % (TNT / 8)) * 8;
                dB[j] = (A_T + r * LDB + nc) * 2;
                pB[j] = Bm + (long long)r * ldb + tile_n + nc;
            }
            stepB = (long long)TKc * ldb;
        } else {
            #pragma unroll
            for (int j = 0; j < JB; j++) {
                int c = tid + j * THREADS;
                int r = c >> 3, kc = (c & 7) * 8;
                dB[j] = (A_T + r * LDA + kc) * 2;
                pB[j] = Bm + (long long)(tile_n + r) * ldb + kc;
            }
            stepB = TKc;
        }
        auto stageF = [&](int bufi) {
            char* base = smraw + bufi * STAGE;
            #pragma unroll
            for (int j = 0; j < JA; j++) { cp16f(base + dA[j], pA[j]); pA[j] += TKc; }
            #pragma unroll
            for (int j = 0; j < JB; j++) { cp16f(base + dB[j], pB[j]); pB[j] += stepB; }
        };
        stageF(0);
        cp_commit();
        int buf = 0;
        for (int it = 0; it < nIter; ++it) {
            if (it + 1 < nIter) { stageF(buf ^ 1); cp_commit(); cp_wait1(); }
            else cp_wait0();
            __syncthreads();
            compute(buf);
            __syncthreads();
            buf ^= 1;
        }
    } else {
        auto stageS = [&](int it, int bufi) {
            const int k0 = it * TKc;
            __half* sA = (__half*)(smraw + bufi * STAGE);
            __half* sB = sA + A_T;
            #pragma unroll
            for (int j = 0; j < JA; j++) {
                int c = tid + j * THREADS;
                int r = c >> 3, kc = (c & 7) * 8;
                int gm = tile_m + r, gk = k0 + kc;
                int bytes = (gm < M && gk + 8 <= Kp) ? 16 : 0;
                const __half* src = bytes ? (A + (long long)gm * lda + gk) : A;
                cp16(sA + r * LDA + kc, src, bytes);
            }
            if (!TRB) {
                #pragma unroll
                for (int j = 0; j < JB; j++) {
                    int c = tid + j * THREADS;
                    int r = c / (TNT / 8), nc = (c % (TNT / 8)) * 8;
                    int gk = k0 + r, gn = tile_n + nc;
                    int bytes = (gk < Kp && gn + 8 <= N) ? 16 : 0;
                    const __half* src = bytes ? (Bm + (long long)gk * ldb + gn) : Bm;
                    cp16(sB + r * LDB + nc, src, bytes);
                }
            } else {
                #pragma unroll
                for (int j = 0; j < JB; j++) {
                    int c = tid + j * THREADS;
                    int r = c >> 3, kc = (c & 7) * 8;
                    int gn = tile_n + r, gk = k0 + kc;
                    int bytes = (gn < N && gk + 8 <= Kp) ? 16 : 0;
                    const __half* src = bytes ? (Bm + (long long)gn * ldb + gk) : Bm;
                    cp16(sB + r * LDA + kc, src, bytes);
                }
            }
        };
        stageS(0, 0);
        cp_commit();
        int buf = 0;
        for (int it = 0; it < nIter; ++it) {
            if (it + 1 < nIter) { stageS(it + 1, buf ^ 1); cp_commit(); cp_wait1(); }
            else cp_wait0();
            __syncthreads();
            compute(buf);
            __syncthreads();
            buf ^= 1;
        }
    }

    // ---- epilogue: whole-tile smem staging + coalesced vector writeback ----
    __syncthreads();   // mainloop done; stage buffers free for reuse

    constexpr int LDC_S = TNT + 4;               // floats; mult of 4 (16B) for wmma
    float* tileS = (float*)smraw;

    #pragma unroll
    for (int mi = 0; mi < FM; mi++)
        #pragma unroll
        for (int ni = 0; ni < FN; ni++)
            wmma::store_matrix_sync(tileS + (wm * WROWS + mi * 16) * LDC_S
                                          + (wn * WCOLS + ni * 16),
                                    cf[mi][ni], LDC_S, wmma::mem_row_major);
    __syncthreads();

    constexpr int CH = TMT * TNT / 4 / THREADS;  // float4 chunks per thread
    #pragma unroll
    for (int j = 0; j < CH; j++) {
        int c = tid + j * THREADS;
        int rr = c / (TNT / 4);
        int cc = (c % (TNT / 4)) * 4;
        int gm = tile_m + rr;
        int gn = tile_n + cc;
        float4 v = *reinterpret_cast<const float4*>(tileS + rr * LDC_S + cc);
        v.x *= alpha; v.y *= alpha; v.z *= alpha; v.w *= alpha;
        if (BIAS) {
            float4 bv = *reinterpret_cast<const float4*>(bias + gn);
            v.x += bv.x; v.y += bv.y; v.z += bv.z; v.w += bv.w;
        }
        if (RELU) {
            v.x = fmaxf(v.x, 0.0f); v.y = fmaxf(v.y, 0.0f);
            v.z = fmaxf(v.z, 0.0f); v.w = fmaxf(v.w, 0.0f);
        }
        if (full) {
            if (OUTH) {
                __half2 h01 = __floats2half2_rn(v.x, v.y);
                __half2 h23 = __floats2half2_rn(v.z, v.w);
                uint2 pk = make_uint2(*(unsigned*)&h01, *(unsigned*)&h23);
                *reinterpret_cast<uint2*>(Ch + (long long)gm * ldc + gn) = pk;
            } else {
                *reinterpret_cast<float4*>(Cf + (long long)gm * ldc + gn) = v;
            }
        } else if (gm < M) {
            float e[4] = { v.x, v.y, v.z, v.w };
            #pragma unroll
            for (int q = 0; q < 4; q++) {
                if (gn + q < N) {
                    if (OUTH) Ch[(long long)gm * ldc + gn + q] = __float2half_rn(e[q]);
                    else      Cf[(long long)gm * ldc + gn + q] = e[q];
                }
            }
        }
    }
}

template<int TMT, int TNT, int NWM, int NWN, int MINB, int CAUSAL,
         bool TRB, bool BIAS, bool RELU, bool OUTH>
static inline void run_gemm(const __half* A, const __half* B, const float* bias,
                            float* Cf, __half* Ch,
                            int M, int N, int K, int lda, int ldb, int ldc,
                            long long sAb, long long sAh, long long sBb, long long sBh,
                            long long sCb, long long sCh, long long sBib,
                            int Hs, int Z, float alpha)
{
    constexpr int SMEM = SmemNeed<TMT, TNT, TRB>::BYTES;
    static bool s_init = false;
    if (!s_init) {
        cudaFuncSetAttribute(gemm_h<TMT,TNT,NWM,NWN,MINB,CAUSAL,TRB,BIAS,RELU,OUTH>,
                             cudaFuncAttributeMaxDynamicSharedMemorySize, SMEM);
        s_init = true;
    }
    dim3 grid((N + TNT - 1) / TNT, (M + TMT - 1) / TMT, Z);
    gemm_h<TMT,TNT,NWM,NWN,MINB,CAUSAL,TRB,BIAS,RELU,OUTH><<<grid, NWM*NWN*32, SMEM>>>(
        A, B, bias, Cf, Ch, M, N, K, lda, ldb, ldc,
        sAb, sAh, sBb, sBh, sCb, sCh, sBib, Hs, alpha);
}

// ---------------- weight conversion (contiguous, 2x float4 per thread) ----------------
__global__ void f2h_kernel(const float4* __restrict__ in, __half2* __restrict__ out, int n4)
{
    int i0 = blockIdx.x * 512 + threadIdx.x;
    #pragma unroll
    for (int k = 0; k < 2; k++) {
        int i = i0 + k * 256;
        if (i < n4) {
            float4 v = in[i];
            out[2 * i]     = __floats2half2_rn(v.x, v.y);
            out[2 * i + 1] = __floats2half2_rn(v.z, v.w);
        }
    }
}

__global__ void bias_copy3(const float* __restrict__ q, const float* __restrict__ k,
                           const float* __restrict__ v, float* __restrict__ o)
{
    int i = blockIdx.x * 256 + threadIdx.x;
    const int n = LL * DH;
    if (i >= n) return;
    o[i]         = q[i];
    o[i + n]     = k[i];
    o[i + 2 * n] = v[i];
}

// ---------------- embedding (half out) ----------------
__global__ void embed_kernel(const float* __restrict__ x, const float* __restrict__ w,
                             const float* __restrict__ b, __half* __restrict__ h)
{
    int idx = blockIdx.x * 256 + threadIdx.x;
    if (idx >= MTOK * DD) return;
    int row = idx / DD, d = idx % DD;
    int s = row % SS;
    const float* xr = x + row * F_IN;
    float acc = b[d];
    #pragma unroll
    for (int f = 0; f < F_IN; f++) acc += xr[f] * w[f * DD + d];
    acc *= 22.627416997969522f;
    float di2 = (float)(2 * (d >> 1));
    float ang = (float)s * expf(di2 * (-9.210340371976184f / (float)DD));
    float pe = (d & 1) ? cosf(ang) : sinf(ang);
    h[idx] = __float2half_rn(acc + pe);
}

// ---------------- causal softmax: fp32 scores -> half probs ----------------
__global__ void softmax_kernel(const float* __restrict__ s, __half* __restrict__ pr)
{
    int row = blockIdx.x * 8 + (threadIdx.x >> 5);
    if (row >= BB * HH * SS) return;
    int lane = threadIdx.x & 31;
    int q = row % SS;
    const float* p = s + (long long)row * SS;
    __half* o = pr + (long long)row * SS;

    float m = -1e30f;
    for (int j = lane; j <= q; j += 32) m = fmaxf(m, p[j]);
    #pragma unroll
    for (int off = 16; off; off >>= 1) m = fmaxf(m, __shfl_xor_sync(0xffffffffu, m, off));

    float sum = 0.0f;
    for (int j = lane; j <= q; j += 32) sum += expf(p[j] - m);
    #pragma unroll
    for (int off = 16; off; off >>= 1) sum += __shfl_xor_sync(0xffffffffu, sum, off);
    float inv = 1.0f / sum;

    for (int j = lane; j < SS; j += 32)
        o[j] = (j <= q) ? __float2half_rn(expf(p[j] - m) * inv) : __float2half_rn(0.0f);
}

// ---------------- fused residual-add + LayerNorm ----------------
__global__ void add_ln_kernel(const float* __restrict__ a, const __half* __restrict__ r,
                              const float* __restrict__ g, const float* __restrict__ bt,
                              __half* __restrict__ o)
{
    int row = blockIdx.x;
    int t = threadIdx.x;
    long long base = (long long)row * DD;
    float x0 = a[base + t]       + __half2float(r[base + t]);
    float x1 = a[base + t + 256] + __half2float(r[base + t + 256]);
    float sm = x0 + x1, sq = x0 * x0 + x1 * x1;
    #pragma unroll
    for (int off = 16; off; off >>= 1) {
        sm += __shfl_xor_sync(0xffffffffu, sm, off);
        sq += __shfl_xor_sync(0xffffffffu, sq, off);
    }
    __shared__ float sh[2][8];
    if ((t & 31) == 0) { sh[0][t >> 5] = sm; sh[1][t >> 5] = sq; }
    __syncthreads();
    float S = 0, Q = 0;
    #pragma unroll
    for (int j = 0; j < 8; j++) { S += sh[0][j]; Q += sh[1][j]; }
    float mean = S * (1.0f / DD);
    float var  = Q * (1.0f / DD) - mean * mean;
    float inv  = rsqrtf(var + 1e-9f);
    o[base + t]       = __float2half_rn((x0 - mean) * inv * g[t]       + bt[t]);
    o[base + t + 256] = __float2half_rn((x1 - mean) * inv * g[t + 256] + bt[t + 256]);
}

// ---------------- final projection ----------------
__global__ void out_kernel(const __half* __restrict__ h, const float* __restrict__ w,
                           const float* __restrict__ b, float* __restrict__ out)
{
    int r = blockIdx.x * 4 + (threadIdx.x >> 5);
    if (r >= BB * NFUT) return;
    int lane = threadIdx.x & 31;
    int bb = r / NFUT, si = r % NFUT;
    const __half* hr = h + ((long long)bb * SS + (SS - NFUT) + si) * DD;
    float acc = 0.0f;
    for (int d = lane; d < DD; d += 32) acc += __half2float(hr[d]) * w[d];
    #pragma unroll
    for (int o = 16; o; o >>= 1) acc += __shfl_xor_sync(0xffffffffu, acc, o);
    if (lane == 0) out[r] = acc + b[0];
}

extern "C" void kernel_launch(void* const* d_in, const int* in_sizes, int n_in,
                              void* d_out, int out_size)
{
    const float* x    = (const float*)d_in[0];
    const float* in_w = (const float*)d_in[2];
    const float* in_b = (const float*)d_in[3];
    const float* wq_w = (const float*)d_in[4];
    const float* wq_b = (const float*)d_in[5];
    const float* wk_w = (const float*)d_in[6];
    const float* wk_b = (const float*)d_in[7];
    const float* wv_w = (const float*)d_in[8];
    const float* wv_b = (const float*)d_in[9];
    const float* dn_w = (const float*)d_in[10];
    const float* dn_b = (const float*)d_in[11];
    const float* mh_w = (const float*)d_in[12];
    const float* mh_b = (const float*)d_in[13];
    const float* mo_w = (const float*)d_in[14];
    const float* mo_b = (const float*)d_in[15];
    const float* ln1g = (const float*)d_in[16];
    const float* ln1b = (const float*)d_in[17];
    const float* ln3g = (const float*)d_in[18];
    const float* ln3b = (const float*)d_in[19];
    const float* ow   = (const float*)d_in[20];
    const float* ob   = (const float*)d_in[21];

    __half *h, *h1, *qkv, *ctx, *p, *mlp;
    float *t, *sc, *bqkv;
    __half *wqkvh, *wdh, *wmhh, *wmoh;
    cudaGetSymbolAddress((void**)&h,     g_h);
    cudaGetSymbolAddress((void**)&h1,    g_h1);
    cudaGetSymbolAddress((void**)&t,     g_t);
    cudaGetSymbolAddress((void**)&qkv,   g_qkv);
    cudaGetSymbolAddress((void**)&ctx,   g_ctx);
    cudaGetSymbolAddress((void**)&sc,    g_s);
    cudaGetSymbolAddress((void**)&p,     g_p);
    cudaGetSymbolAddress((void**)&mlp,   g_mlp);
    cudaGetSymbolAddress((void**)&wqkvh, g_wqkv);
    cudaGetSymbolAddress((void**)&bqkv,  g_bqkv);
    cudaGetSymbolAddress((void**)&wdh,   g_wd);
    cudaGetSymbolAddress((void**)&wmhh,  g_wmh);
    cudaGetSymbolAddress((void**)&wmoh,  g_wmo);

    // weight conversion — all contiguous fast path (no scatter)
    {
        const int n_qkv = LL * DD * DH / 4;   // float4 count per matrix family
        const int n_mlp = LL * DD * HID / 4;
        const long long wsz = (long long)LL * DD * DH;   // halves per family
        f2h_kernel<<<(n_qkv + 511) / 512, 256>>>((const float4*)wq_w, (__half2*)(wqkvh),           n_qkv);
        f2h_kernel<<<(n_qkv + 511) / 512, 256>>>((const float4*)wk_w, (__half2*)(wqkvh + wsz),     n_qkv);
        f2h_kernel<<<(n_qkv + 511) / 512, 256>>>((const float4*)wv_w, (__half2*)(wqkvh + 2 * wsz), n_qkv);
        bias_copy3<<<(LL * DH + 255) / 256, 256>>>(wq_b, wk_b, wv_b, bqkv);
        f2h_kernel<<<(n_qkv + 511) / 512, 256>>>((const float4*)dn_w, (__half2*)wdh,  n_qkv);
        f2h_kernel<<<(n_mlp + 511) / 512, 256>>>((const float4*)mh_w, (__half2*)wmhh, n_mlp);
        f2h_kernel<<<(n_mlp + 511) / 512, 256>>>((const float4*)mo_w, (__half2*)wmoh, n_mlp);
    }

    const float inv_sqrt_d = 0.044194173824159216f;
    const long long QKV_PLANE = (long long)MTOK * DH;    // output plane stride
    const long long W_FAM     = (long long)LL * DD * DH; // weight family stride

    embed_kernel<<<(MTOK * DD + 255) / 256, 256>>>(x, in_w, in_b, h);

    for (int i = 0; i < LL; i++) {
        // batched QKV: z in {Q,K,V}; [10752,512] @ [512,4096] per z (128x128 tile)
        run_gemm<128,128,4,2,2, 0, false,true,false,true>(
            h, wqkvh + (long long)i * DD * DH, bqkv + (long long)i * DH, nullptr, qkv,
            MTOK, DH, DD, DD, DH, DH,
            0, 0,                      // A: same for all z
            0, W_FAM,                  // B: per-z weight family
            0, QKV_PLANE,              // C: per-z output plane
            (long long)LL * DH,        // bias: per-z family stride
            3, 3, 1.0f);

        const __half* Q = qkv;
        const __half* K = qkv + QKV_PLANE;
        const __half* V = qkv + 2 * QKV_PLANE;

        // scores = Q @ K^T * inv_sqrt_d (small tile, TRB, fp32 out, causal tile-skip)
        run_gemm<64,64,2,2,4, 1, true,false,false,false>(
            Q, K, nullptr, sc, nullptr,
            SS, SS, DD, DH, DH, SS,
            (long long)SS * DH, DD,
            (long long)SS * DH, DD,
            (long long)HH * SS * SS, (long long)SS * SS, 0,
            HH, BB * HH, inv_sqrt_d);

        softmax_kernel<<<(BB * HH * SS + 7) / 8, 256>>>(sc, p);

        // context = P @ V (small tile, half out, causal K-truncation)
        run_gemm<64,64,2,2,4, 2, false,false,false,true>(
            p, V, nullptr, nullptr, ctx,
            SS, DD, SS, SS, DH, DH,
            (long long)HH * SS * SS, (long long)SS * SS,
            (long long)SS * DH, DD,
            (long long)SS * DH, DD, 0,
            HH, BB * HH, 1.0f);

        // dn (small tile, fp32 out -> LN)
        run_gemm<64,64,2,2,4, 0, false,true,false,false>(
            ctx, wdh + (long long)i * DH * DD, dn_b + (long long)i * DD, t, nullptr,
            MTOK, DD, DH, DH, DD, DD, 0,0,0,0,0,0,0, 1, 1, 1.0f);

        add_ln_kernel<<<MTOK, 256>>>(t, h, ln1g + (long long)i * DD, ln1b + (long long)i * DD, h1);

        // MLP up (big tile 128x128, relu, half out)
        run_gemm<128,128,4,2,2, 0, false,true,true,true>(
            h1, wmhh + (long long)i * DD * HID, mh_b + (long long)i * HID, nullptr, mlp,
            MTOK, HID, DD, DD, HID, HID, 0,0,0,0,0,0,0, 1, 1, 1.0f);

        // MLP down (small tile, fp32 out -> LN)
        run_gemm<64,64,2,2,4, 0, false,true,false,false>(
            mlp, wmoh + (long long)i * HID * DD, mo_b + (long long)i * DD, t, nullptr,
            MTOK, DD, HID, HID, DD, DD, 0,0,0,0,0,0,0, 1, 1, 1.0f);

        add_ln_kernel<<<MTOK, 256>>>(t, h1, ln3g + (long long)i * DD, ln3b + (long long)i * DD, h);
    }

    out_kernel<<<(BB * NFUT + 3) / 4, 128>>>(h, ow, ob, (float*)d_out);
}

// round 16
// speedup vs baseline: 1.1094x; 1.0227x over previous
#include <cuda_runtime.h>
#include <cuda_fp16.h>
#include <mma.h>
#include <math.h>

using namespace nvcuda;

// ---------------- problem constants ----------------
#define BB 64
#define SS 168
#define F_IN 10
#define DD 512
#define HH 8
#define LL 4
#define HID 2048
#define NFUT 48
#define DH (DD*HH)          // 4096
#define MTOK (BB*SS)        // 10752

// ---------------- scratch ----------------
__device__ __half g_h   [MTOK*DD];
__device__ __half g_h1  [MTOK*DD];
__device__ float  g_t   [MTOK*DD];
__device__ __half g_qkv [3LL*MTOK*DH];     // [3][MTOK][DH] planes: Q,K,V
__device__ __half g_ctx [MTOK*DH];
__device__ float  g_s   [BB*HH*SS*SS];
__device__ __half g_p   [BB*HH*SS*SS];
__device__ __half g_mlp [MTOK*HID];
__device__ __half g_wqkv[3LL*LL*DD*DH];    // [3][LL][DD*DH] contiguous
__device__ float  g_bqkv[3LL*LL*DH];       // [3][LL][DH]
__device__ __half g_wd  [LL*DH*DD];
__device__ __half g_wmh [LL*DD*HID];
__device__ __half g_wmo [LL*HID*DD];

// ---------------- cp.async helpers ----------------
__device__ __forceinline__ void cp16(void* dst, const void* src, int bytes) {
    unsigned d = (unsigned)__cvta_generic_to_shared(dst);
    asm volatile("cp.async.cg.shared.global [%0], [%1], 16, %2;\n"
                 :: "r"(d), "l"(src), "r"(bytes));
}
__device__ __forceinline__ void cp16f(void* dst, const void* src) {
    unsigned d = (unsigned)__cvta_generic_to_shared(dst);
    asm volatile("cp.async.cg.shared.global [%0], [%1], 16;\n"
                 :: "r"(d), "l"(src));
}
__device__ __forceinline__ void cp_commit() {
    asm volatile("cp.async.commit_group;\n" ::: "memory");
}
__device__ __forceinline__ void cp_wait1() {
    asm volatile("cp.async.wait_group 1;\n" ::: "memory");
}
__device__ __forceinline__ void cp_wait0() {
    asm volatile("cp.async.wait_group 0;\n" ::: "memory");
}

// smem size needed per config (stage buffers vs whole-tile epilogue)
template<int TMT, int TNT, bool TRB>
struct SmemNeed {
    static constexpr int LDA = 72;
    static constexpr int A_T = TMT * LDA;
    static constexpr int B_T = TRB ? (TNT * LDA) : (64 * (TNT + 8));
    static constexpr int STAGE2 = 2 * ((A_T + B_T) * 2);
    static constexpr int EPI = TMT * (TNT + 4) * 4;
    static constexpr int BYTES = STAGE2 > EPI ? STAGE2 : EPI;
};

// ================= templated fp16 GEMM (2-stage mainloop + coalesced epilogue) ========
// C = alpha * A[M,K] @ (TRB ? B^T : B) (+bias[+hh*sBib]) (+relu); OUTH: half out.
// CAUSAL: 0 = none; 1 = skip tiles fully above diagonal (scores);
//         2 = truncate K at tile_m+TMT (PV over causal probs; exact, probs==0 there).
template<int TMT, int TNT, int NWM, int NWN, int MINB, int CAUSAL,
         bool TRB, bool BIAS, bool RELU, bool OUTH>
__global__ void __launch_bounds__(NWM*NWN*32, MINB)
gemm_h(const __half* __restrict__ A, const __half* __restrict__ Bm,
       const float* __restrict__ bias, float* __restrict__ Cf, __half* __restrict__ Ch,
       int M, int N, int K, int lda, int ldb, int ldc,
       long long sAb, long long sAh, long long sBb, long long sBh,
       long long sCb, long long sCh, long long sBib, int Hs, float alpha)
{
    constexpr int THREADS = NWM * NWN * 32;
    constexpr int TKc = 64;
    constexpr int LDA = TKc + 8;                 // 72 halves (144B, 16B-mult)
    constexpr int LDB = TNT + 8;
    constexpr int A_T = TMT * LDA;               // halves
    constexpr int B_T = TRB ? (TNT * LDA) : (TKc * LDB);
    constexpr int STAGE = (A_T + B_T) * 2;       // bytes
    constexpr int WROWS = TMT / NWM, WCOLS = TNT / NWN;
    constexpr int FM = WROWS / 16, FN = WCOLS / 16;
    constexpr int JA = TMT * (TKc / 8) / THREADS;
    constexpr int JB = (TRB ? TNT * (TKc / 8) : TKc * (TNT / 8)) / THREADS;

    extern __shared__ char smraw[];

    const int tile_m = blockIdx.y * TMT;
    const int tile_n = blockIdx.x * TNT;

    if (CAUSAL == 1 && tile_n >= tile_m + TMT) return;
    const int Kp = (CAUSAL == 2) ? min(K, tile_m + TMT) : K;

    const int z = blockIdx.z;
    const int b = z / Hs, hh = z % Hs;
    A  += (long long)b * sAb + (long long)hh * sAh;
    Bm += (long long)b * sBb + (long long)hh * sBh;
    if (BIAS) bias += (long long)hh * sBib;
    if (OUTH) Ch += (long long)b * sCb + (long long)hh * sCh;
    else      Cf += (long long)b * sCb + (long long)hh * sCh;

    const int tid  = threadIdx.x;
    const int warp = tid >> 5;
    const int wm = warp % NWM;
    const int wn = warp / NWM;

    wmma::fragment<wmma::accumulator, 16, 16, 16, float> cf[FM][FN];
    #pragma unroll
    for (int i = 0; i < FM; i++)
        #pragma unroll
        for (int j = 0; j < FN; j++)
            wmma::fill_fragment(cf[i][j], 0.0f);

    const int nIter = (Kp + TKc - 1) / TKc;
    const bool full = (tile_m + TMT <= M) && (tile_n + TNT <= N);
    const bool fast = full && ((Kp & (TKc - 1)) == 0);

    auto compute = [&](int bufi) {
        const __half* sA = (const __half*)(smraw + bufi * STAGE);
        const __half* sB = sA + A_T;
        #pragma unroll
        for (int kk = 0; kk < TKc; kk += 16) {
            wmma::fragment<wmma::matrix_a, 16, 16, 16, __half, wmma::row_major> af[FM];
            #pragma unroll
            for (int mi = 0; mi < FM; mi++)
                wmma::load_matrix_sync(af[mi], sA + (wm * WROWS + mi * 16) * LDA + kk, LDA);
            if (!TRB) {
                wmma::fragment<wmma::matrix_b, 16, 16, 16, __half, wmma::row_major> bf[FN];
                #pragma unroll
                for (int ni = 0; ni < FN; ni++)
                    wmma::load_matrix_sync(bf[ni], sB + kk * LDB + (wn * WCOLS + ni * 16), LDB);
                #pragma unroll
                for (int mi = 0; mi < FM; mi++)
                    #pragma unroll
                    for (int ni = 0; ni < FN; ni++)
                        wmma::mma_sync(cf[mi][ni], af[mi], bf[ni], cf[mi][ni]);
            } else {
                wmma::fragment<wmma::matrix_b, 16, 16, 16, __half, wmma::col_major> bf[FN];
                #pragma unroll
                for (int ni = 0; ni < FN; ni++)
                    wmma::load_matrix_sync(bf[ni], sB + (wn * WCOLS + ni * 16) * LDA + kk, LDA);
                #pragma unroll
                for (int mi = 0; mi < FM; mi++)
                    #pragma unroll
                    for (int ni = 0; ni < FN; ni++)
                        wmma::mma_sync(cf[mi][ni], af[mi], bf[ni], cf[mi][ni]);
            }
        }
    };

    if (fast) {
        int dA[JA]; const __half* pA[JA];
        int dB[JB]; const __half* pB[JB];
        long long stepB;
        #pragma unroll
        for (int j = 0; j < JA; j++) {
            int c = tid + j * THREADS;
            int r = c >> 3, kc = (c & 7) * 8;
            dA[j] = (r * LDA + kc) * 2;
            pA[j] = A + (long long)(tile_m + r) * lda + kc;
        }
        if (!TRB) {
            #pragma unroll
            for (int j = 0; j < JB; j++) {
                int c = tid + j * THREADS;
                int r = c / (TNT / 8), nc = (c % (TNT / 8)) * 8;
                dB[j] = (A_T + r * LDB + nc) * 2;
                pB[j] = Bm + (long long)r * ldb + tile_n + nc;
            }
            stepB = (long long)TKc * ldb;
        } else {
            #pragma unroll
            for (int j = 0; j < JB; j++) {
                int c = tid + j * THREADS;
                int r = c >> 3, kc = (c & 7) * 8;
                dB[j] = (A_T + r * LDA + kc) * 2;
                pB[j] = Bm + (long long)(tile_n + r) * ldb + kc;
            }
            stepB = TKc;
        }
        auto stageF = [&](int bufi) {
            char* base = smraw + bufi * STAGE;
            #pragma unroll
            for (int j = 0; j < JA; j++) { cp16f(base + dA[j], pA[j]); pA[j] += TKc; }
            #pragma unroll
            for (int j = 0; j < JB; j++) { cp16f(base + dB[j], pB[j]); pB[j] += stepB; }
        };
        stageF(0);
        cp_commit();
        int buf = 0;
        for (int it = 0; it < nIter; ++it) {
            if (it + 1 < nIter) { stageF(buf ^ 1); cp_commit(); cp_wait1(); }
            else cp_wait0();
            __syncthreads();
            compute(buf);
            __syncthreads();
            buf ^= 1;
        }
    } else {
        auto stageS = [&](int it, int bufi) {
            const int k0 = it * TKc;
            __half* sA = (__half*)(smraw + bufi * STAGE);
            __half* sB = sA + A_T;
            #pragma unroll
            for (int j = 0; j < JA; j++) {
                int c = tid + j * THREADS;
                int r = c >> 3, kc = (c & 7) * 8;
                int gm = tile_m + r, gk = k0 + kc;
                int bytes = (gm < M && gk + 8 <= Kp) ? 16 : 0;
                const __half* src = bytes ? (A + (long long)gm * lda + gk) : A;
                cp16(sA + r * LDA + kc, src, bytes);
            }
            if (!TRB) {
                #pragma unroll
                for (int j = 0; j < JB; j++) {
                    int c = tid + j * THREADS;
                    int r = c / (TNT / 8), nc = (c % (TNT / 8)) * 8;
                    int gk = k0 + r, gn = tile_n + nc;
                    int bytes = (gk < Kp && gn + 8 <= N) ? 16 : 0;
                    const __half* src = bytes ? (Bm + (long long)gk * ldb + gn) : Bm;
                    cp16(sB + r * LDB + nc, src, bytes);
                }
            } else {
                #pragma unroll
                for (int j = 0; j < JB; j++) {
                    int c = tid + j * THREADS;
                    int r = c >> 3, kc = (c & 7) * 8;
                    int gn = tile_n + r, gk = k0 + kc;
                    int bytes = (gn < N && gk + 8 <= Kp) ? 16 : 0;
                    const __half* src = bytes ? (Bm + (long long)gn * ldb + gk) : Bm;
                    cp16(sB + r * LDA + kc, src, bytes);
                }
            }
        };
        stageS(0, 0);
        cp_commit();
        int buf = 0;
        for (int it = 0; it < nIter; ++it) {
            if (it + 1 < nIter) { stageS(it + 1, buf ^ 1); cp_commit(); cp_wait1(); }
            else cp_wait0();
            __syncthreads();
            compute(buf);
            __syncthreads();
            buf ^= 1;
        }
    }

    // ---- epilogue: whole-tile smem staging + coalesced vector writeback ----
    __syncthreads();   // mainloop done; stage buffers free for reuse

    constexpr int LDC_S = TNT + 4;               // floats; mult of 4 (16B) for wmma
    float* tileS = (float*)smraw;

    #pragma unroll
    for (int mi = 0; mi < FM; mi++)
        #pragma unroll
        for (int ni = 0; ni < FN; ni++)
            wmma::store_matrix_sync(tileS + (wm * WROWS + mi * 16) * LDC_S
                                          + (wn * WCOLS + ni * 16),
                                    cf[mi][ni], LDC_S, wmma::mem_row_major);
    __syncthreads();

    constexpr int CH = TMT * TNT / 4 / THREADS;  // float4 chunks per thread
    #pragma unroll
    for (int j = 0; j < CH; j++) {
        int c = tid + j * THREADS;
        int rr = c / (TNT / 4);
        int cc = (c % (TNT / 4)) * 4;
        int gm = tile_m + rr;
        int gn = tile_n + cc;
        float4 v = *reinterpret_cast<const float4*>(tileS + rr * LDC_S + cc);
        v.x *= alpha; v.y *= alpha; v.z *= alpha; v.w *= alpha;
        if (BIAS) {
            float4 bv = *reinterpret_cast<const float4*>(bias + gn);
            v.x += bv.x; v.y += bv.y; v.z += bv.z; v.w += bv.w;
        }
        if (RELU) {
            v.x = fmaxf(v.x, 0.0f); v.y = fmaxf(v.y, 0.0f);
            v.z = fmaxf(v.z, 0.0f); v.w = fmaxf(v.w, 0.0f);
        }
        if (full) {
            if (OUTH) {
                __half2 h01 = __floats2half2_rn(v.x, v.y);
                __half2 h23 = __floats2half2_rn(v.z, v.w);
                uint2 pk = make_uint2(*(unsigned*)&h01, *(unsigned*)&h23);
                *reinterpret_cast<uint2*>(Ch + (long long)gm * ldc + gn) = pk;
            } else {
                *reinterpret_cast<float4*>(Cf + (long long)gm * ldc + gn) = v;
            }
        } else if (gm < M) {
            float e[4] = { v.x, v.y, v.z, v.w };
            #pragma unroll
            for (int q = 0; q < 4; q++) {
                if (gn + q < N) {
                    if (OUTH) Ch[(long long)gm * ldc + gn + q] = __float2half_rn(e[q]);
                    else      Cf[(long long)gm * ldc + gn + q] = e[q];
                }
            }
        }
    }
}

template<int TMT, int TNT, int NWM, int NWN, int MINB, int CAUSAL,
         bool TRB, bool BIAS, bool RELU, bool OUTH>
static inline void run_gemm(const __half* A, const __half* B, const float* bias,
                            float* Cf, __half* Ch,
                            int M, int N, int K, int lda, int ldb, int ldc,
                            long long sAb, long long sAh, long long sBb, long long sBh,
                            long long sCb, long long sCh, long long sBib,
                            int Hs, int Z, float alpha)
{
    constexpr int SMEM = SmemNeed<TMT, TNT, TRB>::BYTES;
    static bool s_init = false;
    if (!s_init) {
        cudaFuncSetAttribute(gemm_h<TMT,TNT,NWM,NWN,MINB,CAUSAL,TRB,BIAS,RELU,OUTH>,
                             cudaFuncAttributeMaxDynamicSharedMemorySize, SMEM);
        s_init = true;
    }
    dim3 grid((N + TNT - 1) / TNT, (M + TMT - 1) / TMT, Z);
    gemm_h<TMT,TNT,NWM,NWN,MINB,CAUSAL,TRB,BIAS,RELU,OUTH><<<grid, NWM*NWN*32, SMEM>>>(
        A, B, bias, Cf, Ch, M, N, K, lda, ldb, ldc,
        sAb, sAh, sBb, sBh, sCb, sCh, sBib, Hs, alpha);
}

// ---------------- weight conversion (contiguous, 2x float4 per thread) ----------------
__global__ void f2h_kernel(const float4* __restrict__ in, __half2* __restrict__ out, int n4)
{
    int i0 = blockIdx.x * 512 + threadIdx.x;
    #pragma unroll
    for (int k = 0; k < 2; k++) {
        int i = i0 + k * 256;
        if (i < n4) {
            float4 v = in[i];
            out[2 * i]     = __floats2half2_rn(v.x, v.y);
            out[2 * i + 1] = __floats2half2_rn(v.z, v.w);
        }
    }
}

__global__ void bias_copy3(const float* __restrict__ q, const float* __restrict__ k,
                           const float* __restrict__ v, float* __restrict__ o)
{
    int i = blockIdx.x * 256 + threadIdx.x;
    const int n = LL * DH;
    if (i >= n) return;
    o[i]         = q[i];
    o[i + n]     = k[i];
    o[i + 2 * n] = v[i];
}

// ---------------- embedding (half out) ----------------
__global__ void embed_kernel(const float* __restrict__ x, const float* __restrict__ w,
                             const float* __restrict__ b, __half* __restrict__ h)
{
    int idx = blockIdx.x * 256 + threadIdx.x;
    if (idx >= MTOK * DD) return;
    int row = idx / DD, d = idx % DD;
    int s = row % SS;
    const float* xr = x + row * F_IN;
    float acc = b[d];
    #pragma unroll
    for (int f = 0; f < F_IN; f++) acc += xr[f] * w[f * DD + d];
    acc *= 22.627416997969522f;
    float di2 = (float)(2 * (d >> 1));
    float ang = (float)s * expf(di2 * (-9.210340371976184f / (float)DD));
    float pe = (d & 1) ? cosf(ang) : sinf(ang);
    h[idx] = __float2half_rn(acc + pe);
}

// ---------------- causal softmax: single-pass, register-cached ----------------
// Bit-identical to the 3-pass version: same load set (predicated), same max/sum
// order (lane-strided), discarded lanes contribute exact +0.0f to the sum.
__global__ void softmax_kernel(const float* __restrict__ s, __half* __restrict__ pr)
{
    int row = blockIdx.x * 8 + (threadIdx.x >> 5);
    if (row >= BB * HH * SS) return;
    int lane = threadIdx.x & 31;
    int q = row % SS;
    const float* p = s + (long long)row * SS;
    __half* o = pr + (long long)row * SS;

    float pv[6];
    float m = -1e30f;
    #pragma unroll
    for (int c = 0; c < 6; c++) {
        int j = lane + c * 32;
        pv[c] = (j <= q) ? p[j] : -1e30f;
        m = fmaxf(m, pv[c]);
    }
    #pragma unroll
    for (int off = 16; off; off >>= 1) m = fmaxf(m, __shfl_xor_sync(0xffffffffu, m, off));

    float e[6];
    float sum = 0.0f;
    #pragma unroll
    for (int c = 0; c < 6; c++) {
        int j = lane + c * 32;
        e[c] = (j <= q) ? expf(pv[c] - m) : 0.0f;
        sum += e[c];
    }
    #pragma unroll
    for (int off = 16; off; off >>= 1) sum += __shfl_xor_sync(0xffffffffu, sum, off);
    float inv = 1.0f / sum;

    #pragma unroll
    for (int c = 0; c < 6; c++) {
        int j = lane + c * 32;
        if (j < SS)
            o[j] = (j <= q) ? __float2half_rn(e[c] * inv) : __float2half_rn(0.0f);
    }
}

// ---------------- fused residual-add + LayerNorm ----------------
__global__ void add_ln_kernel(const float* __restrict__ a, const __half* __restrict__ r,
                              const float* __restrict__ g, const float* __restrict__ bt,
                              __half* __restrict__ o)
{
    int row = blockIdx.x;
    int t = threadIdx.x;
    long long base = (long long)row * DD;
    float x0 = a[base + t]       + __half2float(r[base + t]);
    float x1 = a[base + t + 256] + __half2float(r[base + t + 256]);
    float sm = x0 + x1, sq = x0 * x0 + x1 * x1;
    #pragma unroll
    for (int off = 16; off; off >>= 1) {
        sm += __shfl_xor_sync(0xffffffffu, sm, off);
        sq += __shfl_xor_sync(0xffffffffu, sq, off);
    }
    __shared__ float sh[2][8];
    if ((t & 31) == 0) { sh[0][t >> 5] = sm; sh[1][t >> 5] = sq; }
    __syncthreads();
    float S = 0, Q = 0;
    #pragma unroll
    for (int j = 0; j < 8; j++) { S += sh[0][j]; Q += sh[1][j]; }
    float mean = S * (1.0f / DD);
    float var  = Q * (1.0f / DD) - mean * mean;
    float inv  = rsqrtf(var + 1e-9f);
    o[base + t]       = __float2half_rn((x0 - mean) * inv * g[t]       + bt[t]);
    o[base + t + 256] = __float2half_rn((x1 - mean) * inv * g[t + 256] + bt[t + 256]);
}

// ---------------- final projection ----------------
__global__ void out_kernel(const __half* __restrict__ h, const float* __restrict__ w,
                           const float* __restrict__ b, float* __restrict__ out)
{
    int r = blockIdx.x * 4 + (threadIdx.x >> 5);
    if (r >= BB * NFUT) return;
    int lane = threadIdx.x & 31;
    int bb = r / NFUT, si = r % NFUT;
    const __half* hr = h + ((long long)bb * SS + (SS - NFUT) + si) * DD;
    float acc = 0.0f;
    for (int d = lane; d < DD; d += 32) acc += __half2float(hr[d]) * w[d];
    #pragma unroll
    for (int o = 16; o; o >>= 1) acc += __shfl_xor_sync(0xffffffffu, acc, o);
    if (lane == 0) out[r] = acc + b[0];
}

extern "C" void kernel_launch(void* const* d_in, const int* in_sizes, int n_in,
                              void* d_out, int out_size)
{
    const float* x    = (const float*)d_in[0];
    const float* in_w = (const float*)d_in[2];
    const float* in_b = (const float*)d_in[3];
    const float* wq_w = (const float*)d_in[4];
    const float* wq_b = (const float*)d_in[5];
    const float* wk_w = (const float*)d_in[6];
    const float* wk_b = (const float*)d_in[7];
    const float* wv_w = (const float*)d_in[8];
    const float* wv_b = (const float*)d_in[9];
    const float* dn_w = (const float*)d_in[10];
    const float* dn_b = (const float*)d_in[11];
    const float* mh_w = (const float*)d_in[12];
    const float* mh_b = (const float*)d_in[13];
    const float* mo_w = (const float*)d_in[14];
    const float* mo_b = (const float*)d_in[15];
    const float* ln1g = (const float*)d_in[16];
    const float* ln1b = (const float*)d_in[17];
    const float* ln3g = (const float*)d_in[18];
    const float* ln3b = (const float*)d_in[19];
    const float* ow   = (const float*)d_in[20];
    const float* ob   = (const float*)d_in[21];

    __half *h, *h1, *qkv, *ctx, *p, *mlp;
    float *t, *sc, *bqkv;
    __half *wqkvh, *wdh, *wmhh, *wmoh;
    cudaGetSymbolAddress((void**)&h,     g_h);
    cudaGetSymbolAddress((void**)&h1,    g_h1);
    cudaGetSymbolAddress((void**)&t,     g_t);
    cudaGetSymbolAddress((void**)&qkv,   g_qkv);
    cudaGetSymbolAddress((void**)&ctx,   g_ctx);
    cudaGetSymbolAddress((void**)&sc,    g_s);
    cudaGetSymbolAddress((void**)&p,     g_p);
    cudaGetSymbolAddress((void**)&mlp,   g_mlp);
    cudaGetSymbolAddress((void**)&wqkvh, g_wqkv);
    cudaGetSymbolAddress((void**)&bqkv,  g_bqkv);
    cudaGetSymbolAddress((void**)&wdh,   g_wd);
    cudaGetSymbolAddress((void**)&wmhh,  g_wmh);
    cudaGetSymbolAddress((void**)&wmoh,  g_wmo);

    // weight conversion — all contiguous fast path (no scatter)
    {
        const int n_qkv = LL * DD * DH / 4;   // float4 count per matrix family
        const int n_mlp = LL * DD * HID / 4;
        const long long wsz = (long long)LL * DD * DH;   // halves per family
        f2h_kernel<<<(n_qkv + 511) / 512, 256>>>((const float4*)wq_w, (__half2*)(wqkvh),           n_qkv);
        f2h_kernel<<<(n_qkv + 511) / 512, 256>>>((const float4*)wk_w, (__half2*)(wqkvh + wsz),     n_qkv);
        f2h_kernel<<<(n_qkv + 511) / 512, 256>>>((const float4*)wv_w, (__half2*)(wqkvh + 2 * wsz), n_qkv);
        bias_copy3<<<(LL * DH + 255) / 256, 256>>>(wq_b, wk_b, wv_b, bqkv);
        f2h_kernel<<<(n_qkv + 511) / 512, 256>>>((const float4*)dn_w, (__half2*)wdh,  n_qkv);
        f2h_kernel<<<(n_mlp + 511) / 512, 256>>>((const float4*)mh_w, (__half2*)wmhh, n_mlp);
        f2h_kernel<<<(n_mlp + 511) / 512, 256>>>((const float4*)mo_w, (__half2*)wmoh, n_mlp);
    }

    const float inv_sqrt_d = 0.044194173824159216f;
    const long long QKV_PLANE = (long long)MTOK * DH;    // output plane stride
    const long long W_FAM     = (long long)LL * DD * DH; // weight family stride

    embed_kernel<<<(MTOK * DD + 255) / 256, 256>>>(x, in_w, in_b, h);

    for (int i = 0; i < LL; i++) {
        // batched QKV: z in {Q,K,V}; [10752,512] @ [512,4096] per z (128x128 tile)
        run_gemm<128,128,4,2,2, 0, false,true,false,true>(
            h, wqkvh + (long long)i * DD * DH, bqkv + (long long)i * DH, nullptr, qkv,
            MTOK, DH, DD, DD, DH, DH,
            0, 0,                      // A: same for all z
            0, W_FAM,                  // B: per-z weight family
            0, QKV_PLANE,              // C: per-z output plane
            (long long)LL * DH,        // bias: per-z family stride
            3, 3, 1.0f);

        const __half* Q = qkv;
        const __half* K = qkv + QKV_PLANE;
        const __half* V = qkv + 2 * QKV_PLANE;

        // scores = Q @ K^T * inv_sqrt_d (64x64 tile, TRB, fp32 out, causal tile-skip)
        run_gemm<64,64,2,2,4, 1, true,false,false,false>(
            Q, K, nullptr, sc, nullptr,
            SS, SS, DD, DH, DH, SS,
            (long long)SS * DH, DD,
            (long long)SS * DH, DD,
            (long long)HH * SS * SS, (long long)SS * SS, 0,
            HH, BB * HH, inv_sqrt_d);

        softmax_kernel<<<(BB * HH * SS + 7) / 8, 256>>>(sc, p);

        // context = P @ V (64x128 tile: mma ratio 1.33, half the barriers; K-truncation)
        run_gemm<64,128,2,2,4, 2, false,false,false,true>(
            p, V, nullptr, nullptr, ctx,
            SS, DD, SS, SS, DH, DH,
            (long long)HH * SS * SS, (long long)SS * SS,
            (long long)SS * DH, DD,
            (long long)SS * DH, DD, 0,
            HH, BB * HH, 1.0f);

        // dn (small tile, fp32 out -> LN)
        run_gemm<64,64,2,2,4, 0, false,true,false,false>(
            ctx, wdh + (long long)i * DH * DD, dn_b + (long long)i * DD, t, nullptr,
            MTOK, DD, DH, DH, DD, DD, 0,0,0,0,0,0,0, 1, 1, 1.0f);

        add_ln_kernel<<<MTOK, 256>>>(t, h, ln1g + (long long)i * DD, ln1b + (long long)i * DD, h1);

        // MLP up (big tile 128x128, relu, half out)
        run_gemm<128,128,4,2,2, 0, false,true,true,true>(
            h1, wmhh + (long long)i * DD * HID, mh_b + (long long)i * HID, nullptr, mlp,
            MTOK, HID, DD, DD, HID, HID, 0,0,0,0,0,0,0, 1, 1, 1.0f);

        // MLP down (small tile, fp32 out -> LN)
        run_gemm<64,64,2,2,4, 0, false,true,false,false>(
            mlp, wmoh + (long long)i * HID * DD, mo_b + (long long)i * DD, t, nullptr,
            MTOK, DD, HID, HID, DD, DD, 0,0,0,0,0,0,0, 1, 1, 1.0f);

        add_ln_kernel<<<MTOK, 256>>>(t, h1, ln3g + (long long)i * DD, ln3b + (long long)i * DD, h);
    }

    out_kernel<<<(BB * NFUT + 3) / 4, 128>>>(h, ow, ob, (float*)d_out);
}

// round 17
// speedup vs baseline: 1.1176x; 1.0075x over previous
#include <cuda_runtime.h>
#include <cuda_fp16.h>
#include <mma.h>
#include <math.h>

using namespace nvcuda;

// ---------------- problem constants ----------------
#define BB 64
#define SS 168
#define F_IN 10
#define DD 512
#define HH 8
#define LL 4
#define HID 2048
#define NFUT 48
#define DH (DD*HH)          // 4096
#define MTOK (BB*SS)        // 10752

// ---------------- scratch ----------------
__device__ __half g_h   [MTOK*DD];
__device__ __half g_h1  [MTOK*DD];
__device__ float  g_t   [MTOK*DD];
__device__ __half g_qkv [3LL*MTOK*DH];     // [3][MTOK][DH] planes: Q,K,V
__device__ __half g_ctx [MTOK*DH];
__device__ float  g_s   [BB*HH*SS*SS];
__device__ __half g_p   [BB*HH*SS*SS];
__device__ __half g_mlp [MTOK*HID];
__device__ __half g_wqkv[3LL*LL*DD*DH];    // [3][LL][DD*DH] contiguous
__device__ float  g_bqkv[3LL*LL*DH];       // [3][LL][DH]
__device__ __half g_wd  [LL*DH*DD];
__device__ __half g_wmh [LL*DD*HID];
__device__ __half g_wmo [LL*HID*DD];

// ---------------- cp.async helpers ----------------
__device__ __forceinline__ void cp16(void* dst, const void* src, int bytes) {
    unsigned d = (unsigned)__cvta_generic_to_shared(dst);
    asm volatile("cp.async.cg.shared.global [%0], [%1], 16, %2;\n"
                 :: "r"(d), "l"(src), "r"(bytes));
}
__device__ __forceinline__ void cp16f(void* dst, const void* src) {
    unsigned d = (unsigned)__cvta_generic_to_shared(dst);
    asm volatile("cp.async.cg.shared.global [%0], [%1], 16;\n"
                 :: "r"(d), "l"(src));
}
__device__ __forceinline__ void cp_commit() {
    asm volatile("cp.async.commit_group;\n" ::: "memory");
}
__device__ __forceinline__ void cp_wait1() {
    asm volatile("cp.async.wait_group 1;\n" ::: "memory");
}
__device__ __forceinline__ void cp_wait0() {
    asm volatile("cp.async.wait_group 0;\n" ::: "memory");
}

// smem size needed per config (stage buffers vs whole-tile epilogue)
template<int TMT, int TNT, bool TRB>
struct SmemNeed {
    static constexpr int LDA = 72;
    static constexpr int A_T = TMT * LDA;
    static constexpr int B_T = TRB ? (TNT * LDA) : (64 * (TNT + 8));
    static constexpr int STAGE2 = 2 * ((A_T + B_T) * 2);
    static constexpr int EPI = TMT * (TNT + 4) * 4;
    static constexpr int BYTES = STAGE2 > EPI ? STAGE2 : EPI;
};

// ================= templated fp16 GEMM (2-stage mainloop + coalesced epilogue) ========
// C = alpha * A[M,K] @ (TRB ? B^T : B) (+bias[+hh*sBib]) (+relu); OUTH: half out.
// CAUSAL: 0 = none; 1 = skip tiles fully above diagonal (scores);
//         2 = truncate K at tile_m+TMT (PV over causal probs; exact, probs==0 there).
template<int TMT, int TNT, int NWM, int NWN, int MINB, int CAUSAL,
         bool TRB, bool BIAS, bool RELU, bool OUTH>
__global__ void __launch_bounds__(NWM*NWN*32, MINB)
gemm_h(const __half* __restrict__ A, const __half* __restrict__ Bm,
       const float* __restrict__ bias, float* __restrict__ Cf, __half* __restrict__ Ch,
       int M, int N, int K, int lda, int ldb, int ldc,
       long long sAb, long long sAh, long long sBb, long long sBh,
       long long sCb, long long sCh, long long sBib, int Hs, float alpha)
{
    constexpr int THREADS = NWM * NWN * 32;
    constexpr int TKc = 64;
    constexpr int LDA = TKc + 8;                 // 72 halves (144B, 16B-mult)
    constexpr int LDB = TNT + 8;
    constexpr int A_T = TMT * LDA;               // halves
    constexpr int B_T = TRB ? (TNT * LDA) : (TKc * LDB);
    constexpr int STAGE = (A_T + B_T) * 2;       // bytes
    constexpr int WROWS = TMT / NWM, WCOLS = TNT / NWN;
    constexpr int FM = WROWS / 16, FN = WCOLS / 16;
    constexpr int JA = TMT * (TKc / 8) / THREADS;
    constexpr int JB = (TRB ? TNT * (TKc / 8) : TKc * (TNT / 8)) / THREADS;

    extern __shared__ char smraw[];

    const int tile_m = blockIdx.y * TMT;
    const int tile_n = blockIdx.x * TNT;

    if (CAUSAL == 1 && tile_n >= tile_m + TMT) return;
    const int Kp = (CAUSAL == 2) ? min(K, tile_m + TMT) : K;

    const int z = blockIdx.z;
    const int b = z / Hs, hh = z % Hs;
    A  += (long long)b * sAb + (long long)hh * sAh;
    Bm += (long long)b * sBb + (long long)hh * sBh;
    if (BIAS) bias += (long long)hh * sBib;
    if (OUTH) Ch += (long long)b * sCb + (long long)hh * sCh;
    else      Cf += (long long)b * sCb + (long long)hh * sCh;

    const int tid  = threadIdx.x;
    const int warp = tid >> 5;
    const int wm = warp % NWM;
    const int wn = warp / NWM;

    wmma::fragment<wmma::accumulator, 16, 16, 16, float> cf[FM][FN];
    #pragma unroll
    for (int i = 0; i < FM; i++)
        #pragma unroll
        for (int j = 0; j < FN; j++)
            wmma::fill_fragment(cf[i][j], 0.0f);

    const int nIter = (Kp + TKc - 1) / TKc;
    const bool full = (tile_m + TMT <= M) && (tile_n + TNT <= N);
    const bool fast = full && ((Kp & (TKc - 1)) == 0);

    auto compute = [&](int bufi) {
        const __half* sA = (const __half*)(smraw + bufi * STAGE);
        const __half* sB = sA + A_T;
        #pragma unroll
        for (int kk = 0; kk < TKc; kk += 16) {
            wmma::fragment<wmma::matrix_a, 16, 16, 16, __half, wmma::row_major> af[FM];
            #pragma unroll
            for (int mi = 0; mi < FM; mi++)
                wmma::load_matrix_sync(af[mi], sA + (wm * WROWS + mi * 16) * LDA + kk, LDA);
            if (!TRB) {
                wmma::fragment<wmma::matrix_b, 16, 16, 16, __half, wmma::row_major> bf[FN];
                #pragma unroll
                for (int ni = 0; ni < FN; ni++)
                    wmma::load_matrix_sync(bf[ni], sB + kk * LDB + (wn * WCOLS + ni * 16), LDB);
                #pragma unroll
                for (int mi = 0; mi < FM; mi++)
                    #pragma unroll
                    for (int ni = 0; ni < FN; ni++)
                        wmma::mma_sync(cf[mi][ni], af[mi], bf[ni], cf[mi][ni]);
            } else {
                wmma::fragment<wmma::matrix_b, 16, 16, 16, __half, wmma::col_major> bf[FN];
                #pragma unroll
                for (int ni = 0; ni < FN; ni++)
                    wmma::load_matrix_sync(bf[ni], sB + (wn * WCOLS + ni * 16) * LDA + kk, LDA);
                #pragma unroll
                for (int mi = 0; mi < FM; mi++)
                    #pragma unroll
                    for (int ni = 0; ni < FN; ni++)
                        wmma::mma_sync(cf[mi][ni], af[mi], bf[ni], cf[mi][ni]);
            }
        }
    };

    if (fast) {
        int dA[JA]; const __half* pA[JA];
        int dB[JB]; const __half* pB[JB];
        long long stepB;
        #pragma unroll
        for (int j = 0; j < JA; j++) {
            int c = tid + j * THREADS;
            int r = c >> 3, kc = (c & 7) * 8;
            dA[j] = (r * LDA + kc) * 2;
            pA[j] = A + (long long)(tile_m + r) * lda + kc;
        }
        if (!TRB) {
            #pragma unroll
            for (int j = 0; j < JB; j++) {
                int c = tid + j * THREADS;
                int r = c / (TNT / 8), nc = (c % (TNT / 8)) * 8;
                dB[j] = (A_T + r * LDB + nc) * 2;
                pB[j] = Bm + (long long)r * ldb + tile_n + nc;
            }
            stepB = (long long)TKc * ldb;
        } else {
            #pragma unroll
            for (int j = 0; j < JB; j++) {
                int c = tid + j * THREADS;
                int r = c >> 3, kc = (c & 7) * 8;
                dB[j] = (A_T + r * LDA + kc) * 2;
                pB[j] = Bm + (long long)(tile_n + r) * ldb + kc;
            }
            stepB = TKc;
        }
        auto stageF = [&](int bufi) {
            char* base = smraw + bufi * STAGE;
            #pragma unroll
            for (int j = 0; j < JA; j++) { cp16f(base + dA[j], pA[j]); pA[j] += TKc; }
            #pragma unroll
            for (int j = 0; j < JB; j++) { cp16f(base + dB[j], pB[j]); pB[j] += stepB; }
        };
        stageF(0);
        cp_commit();
        int buf = 0;
        for (int it = 0; it < nIter; ++it) {
            if (it + 1 < nIter) { stageF(buf ^ 1); cp_commit(); cp_wait1(); }
            else cp_wait0();
            __syncthreads();
            compute(buf);
            __syncthreads();
            buf ^= 1;
        }
    } else {
        auto stageS = [&](int it, int bufi) {
            const int k0 = it * TKc;
            __half* sA = (__half*)(smraw + bufi * STAGE);
            __half* sB = sA + A_T;
            #pragma unroll
            for (int j = 0; j < JA; j++) {
                int c = tid + j * THREADS;
                int r = c >> 3, kc = (c & 7) * 8;
                int gm = tile_m + r, gk = k0 + kc;
                int bytes = (gm < M && gk + 8 <= Kp) ? 16 : 0;
                const __half* src = bytes ? (A + (long long)gm * lda + gk) : A;
                cp16(sA + r * LDA + kc, src, bytes);
            }
            if (!TRB) {
                #pragma unroll
                for (int j = 0; j < JB; j++) {
                    int c = tid + j * THREADS;
                    int r = c / (TNT / 8), nc = (c % (TNT / 8)) * 8;
                    int gk = k0 + r, gn = tile_n + nc;
                    int bytes = (gk < Kp && gn + 8 <= N) ? 16 : 0;
                    const __half* src = bytes ? (Bm + (long long)gk * ldb + gn) : Bm;
                    cp16(sB + r * LDB + nc, src, bytes);
                }
            } else {
                #pragma unroll
                for (int j = 0; j < JB; j++) {
                    int c = tid + j * THREADS;
                    int r = c >> 3, kc = (c & 7) * 8;
                    int gn = tile_n + r, gk = k0 + kc;
                    int bytes = (gn < N && gk + 8 <= Kp) ? 16 : 0;
                    const __half* src = bytes ? (Bm + (long long)gn * ldb + gk) : Bm;
                    cp16(sB + r * LDA + kc, src, bytes);
                }
            }
        };
        stageS(0, 0);
        cp_commit();
        int buf = 0;
        for (int it = 0; it < nIter; ++it) {
            if (it + 1 < nIter) { stageS(it + 1, buf ^ 1); cp_commit(); cp_wait1(); }
            else cp_wait0();
            __syncthreads();
            compute(buf);
            __syncthreads();
            buf ^= 1;
        }
    }

    // ---- epilogue: whole-tile smem staging + coalesced vector writeback ----
    __syncthreads();   // mainloop done; stage buffers free for reuse

    constexpr int LDC_S = TNT + 4;               // floats; mult of 4 (16B) for wmma
    float* tileS = (float*)smraw;

    #pragma unroll
    for (int mi = 0; mi < FM; mi++)
        #pragma unroll
        for (int ni = 0; ni < FN; ni++)
            wmma::store_matrix_sync(tileS + (wm * WROWS + mi * 16) * LDC_S
                                          + (wn * WCOLS + ni * 16),
                                    cf[mi][ni], LDC_S, wmma::mem_row_major);
    __syncthreads();

    constexpr int CH = TMT * TNT / 4 / THREADS;  // float4 chunks per thread
    #pragma unroll
    for (int j = 0; j < CH; j++) {
        int c = tid + j * THREADS;
        int rr = c / (TNT / 4);
        int cc = (c % (TNT / 4)) * 4;
        int gm = tile_m + rr;
        int gn = tile_n + cc;
        float4 v = *reinterpret_cast<const float4*>(tileS + rr * LDC_S + cc);
        v.x *= alpha; v.y *= alpha; v.z *= alpha; v.w *= alpha;
        if (BIAS) {
            float4 bv = *reinterpret_cast<const float4*>(bias + gn);
            v.x += bv.x; v.y += bv.y; v.z += bv.z; v.w += bv.w;
        }
        if (RELU) {
            v.x = fmaxf(v.x, 0.0f); v.y = fmaxf(v.y, 0.0f);
            v.z = fmaxf(v.z, 0.0f); v.w = fmaxf(v.w, 0.0f);
        }
        if (full) {
            if (OUTH) {
                __half2 h01 = __floats2half2_rn(v.x, v.y);
                __half2 h23 = __floats2half2_rn(v.z, v.w);
                uint2 pk = make_uint2(*(unsigned*)&h01, *(unsigned*)&h23);
                *reinterpret_cast<uint2*>(Ch + (long long)gm * ldc + gn) = pk;
            } else {
                *reinterpret_cast<float4*>(Cf + (long long)gm * ldc + gn) = v;
            }
        } else if (gm < M) {
            float e[4] = { v.x, v.y, v.z, v.w };
            #pragma unroll
            for (int q = 0; q < 4; q++) {
                if (gn + q < N) {
                    if (OUTH) Ch[(long long)gm * ldc + gn + q] = __float2half_rn(e[q]);
                    else      Cf[(long long)gm * ldc + gn + q] = e[q];
                }
            }
        }
    }
}

template<int TMT, int TNT, int NWM, int NWN, int MINB, int CAUSAL,
         bool TRB, bool BIAS, bool RELU, bool OUTH>
static inline void run_gemm(const __half* A, const __half* B, const float* bias,
                            float* Cf, __half* Ch,
                            int M, int N, int K, int lda, int ldb, int ldc,
                            long long sAb, long long sAh, long long sBb, long long sBh,
                            long long sCb, long long sCh, long long sBib,
                            int Hs, int Z, float alpha)
{
    constexpr int SMEM = SmemNeed<TMT, TNT, TRB>::BYTES;
    static bool s_init = false;
    if (!s_init) {
        cudaFuncSetAttribute(gemm_h<TMT,TNT,NWM,NWN,MINB,CAUSAL,TRB,BIAS,RELU,OUTH>,
                             cudaFuncAttributeMaxDynamicSharedMemorySize, SMEM);
        s_init = true;
    }
    dim3 grid((N + TNT - 1) / TNT, (M + TMT - 1) / TMT, Z);
    gemm_h<TMT,TNT,NWM,NWN,MINB,CAUSAL,TRB,BIAS,RELU,OUTH><<<grid, NWM*NWN*32, SMEM>>>(
        A, B, bias, Cf, Ch, M, N, K, lda, ldb, ldc,
        sAb, sAh, sBb, sBh, sCb, sCh, sBib, Hs, alpha);
}

// ---------------- weight conversion (contiguous, 2x float4 per thread) ----------------
__global__ void f2h_kernel(const float4* __restrict__ in, __half2* __restrict__ out, int n4)
{
    int i0 = blockIdx.x * 512 + threadIdx.x;
    #pragma unroll
    for (int k = 0; k < 2; k++) {
        int i = i0 + k * 256;
        if (i < n4) {
            float4 v = in[i];
            out[2 * i]     = __floats2half2_rn(v.x, v.y);
            out[2 * i + 1] = __floats2half2_rn(v.z, v.w);
        }
    }
}

__global__ void bias_copy3(const float* __restrict__ q, const float* __restrict__ k,
                           const float* __restrict__ v, float* __restrict__ o)
{
    int i = blockIdx.x * 256 + threadIdx.x;
    const int n = LL * DH;
    if (i >= n) return;
    o[i]         = q[i];
    o[i + n]     = k[i];
    o[i + 2 * n] = v[i];
}

// ---------------- embedding (half out) ----------------
__global__ void embed_kernel(const float* __restrict__ x, const float* __restrict__ w,
                             const float* __restrict__ b, __half* __restrict__ h)
{
    int idx = blockIdx.x * 256 + threadIdx.x;
    if (idx >= MTOK * DD) return;
    int row = idx / DD, d = idx % DD;
    int s = row % SS;
    const float* xr = x + row * F_IN;
    float acc = b[d];
    #pragma unroll
    for (int f = 0; f < F_IN; f++) acc += xr[f] * w[f * DD + d];
    acc *= 22.627416997969522f;
    float di2 = (float)(2 * (d >> 1));
    float ang = (float)s * expf(di2 * (-9.210340371976184f / (float)DD));
    float pe = (d & 1) ? cosf(ang) : sinf(ang);
    h[idx] = __float2half_rn(acc + pe);
}

// ---------------- causal softmax: single-pass, register-cached ----------------
__global__ void softmax_kernel(const float* __restrict__ s, __half* __restrict__ pr)
{
    int row = blockIdx.x * 8 + (threadIdx.x >> 5);
    if (row >= BB * HH * SS) return;
    int lane = threadIdx.x & 31;
    int q = row % SS;
    const float* p = s + (long long)row * SS;
    __half* o = pr + (long long)row * SS;

    float pv[6];
    float m = -1e30f;
    #pragma unroll
    for (int c = 0; c < 6; c++) {
        int j = lane + c * 32;
        pv[c] = (j <= q) ? p[j] : -1e30f;
        m = fmaxf(m, pv[c]);
    }
    #pragma unroll
    for (int off = 16; off; off >>= 1) m = fmaxf(m, __shfl_xor_sync(0xffffffffu, m, off));

    float e[6];
    float sum = 0.0f;
    #pragma unroll
    for (int c = 0; c < 6; c++) {
        int j = lane + c * 32;
        e[c] = (j <= q) ? expf(pv[c] - m) : 0.0f;
        sum += e[c];
    }
    #pragma unroll
    for (int off = 16; off; off >>= 1) sum += __shfl_xor_sync(0xffffffffu, sum, off);
    float inv = 1.0f / sum;

    #pragma unroll
    for (int c = 0; c < 6; c++) {
        int j = lane + c * 32;
        if (j < SS)
            o[j] = (j <= q) ? __float2half_rn(e[c] * inv) : __float2half_rn(0.0f);
    }
}

// ---------------- fused residual-add + LayerNorm ----------------
__global__ void add_ln_kernel(const float* __restrict__ a, const __half* __restrict__ r,
                              const float* __restrict__ g, const float* __restrict__ bt,
                              __half* __restrict__ o)
{
    int row = blockIdx.x;
    int t = threadIdx.x;
    long long base = (long long)row * DD;
    float x0 = a[base + t]       + __half2float(r[base + t]);
    float x1 = a[base + t + 256] + __half2float(r[base + t + 256]);
    float sm = x0 + x1, sq = x0 * x0 + x1 * x1;
    #pragma unroll
    for (int off = 16; off; off >>= 1) {
        sm += __shfl_xor_sync(0xffffffffu, sm, off);
        sq += __shfl_xor_sync(0xffffffffu, sq, off);
    }
    __shared__ float sh[2][8];
    if ((t & 31) == 0) { sh[0][t >> 5] = sm; sh[1][t >> 5] = sq; }
    __syncthreads();
    float S = 0, Q = 0;
    #pragma unroll
    for (int j = 0; j < 8; j++) { S += sh[0][j]; Q += sh[1][j]; }
    float mean = S * (1.0f / DD);
    float var  = Q * (1.0f / DD) - mean * mean;
    float inv  = rsqrtf(var + 1e-9f);
    o[base + t]       = __float2half_rn((x0 - mean) * inv * g[t]       + bt[t]);
    o[base + t + 256] = __float2half_rn((x1 - mean) * inv * g[t + 256] + bt[t + 256]);
}

// ---------------- final projection ----------------
__global__ void out_kernel(const __half* __restrict__ h, const float* __restrict__ w,
                           const float* __restrict__ b, float* __restrict__ out)
{
    int r = blockIdx.x * 4 + (threadIdx.x >> 5);
    if (r >= BB * NFUT) return;
    int lane = threadIdx.x & 31;
    int bb = r / NFUT, si = r % NFUT;
    const __half* hr = h + ((long long)bb * SS + (SS - NFUT) + si) * DD;
    float acc = 0.0f;
    for (int d = lane; d < DD; d += 32) acc += __half2float(hr[d]) * w[d];
    #pragma unroll
    for (int o = 16; o; o >>= 1) acc += __shfl_xor_sync(0xffffffffu, acc, o);
    if (lane == 0) out[r] = acc + b[0];
}

extern "C" void kernel_launch(void* const* d_in, const int* in_sizes, int n_in,
                              void* d_out, int out_size)
{
    const float* x    = (const float*)d_in[0];
    const float* in_w = (const float*)d_in[2];
    const float* in_b = (const float*)d_in[3];
    const float* wq_w = (const float*)d_in[4];
    const float* wq_b = (const float*)d_in[5];
    const float* wk_w = (const float*)d_in[6];
    const float* wk_b = (const float*)d_in[7];
    const float* wv_w = (const float*)d_in[8];
    const float* wv_b = (const float*)d_in[9];
    const float* dn_w = (const float*)d_in[10];
    const float* dn_b = (const float*)d_in[11];
    const float* mh_w = (const float*)d_in[12];
    const float* mh_b = (const float*)d_in[13];
    const float* mo_w = (const float*)d_in[14];
    const float* mo_b = (const float*)d_in[15];
    const float* ln1g = (const float*)d_in[16];
    const float* ln1b = (const float*)d_in[17];
    const float* ln3g = (const float*)d_in[18];
    const float* ln3b = (const float*)d_in[19];
    const float* ow   = (const float*)d_in[20];
    const float* ob   = (const float*)d_in[21];

    __half *h, *h1, *qkv, *ctx, *p, *mlp;
    float *t, *sc, *bqkv;
    __half *wqkvh, *wdh, *wmhh, *wmoh;
    cudaGetSymbolAddress((void**)&h,     g_h);
    cudaGetSymbolAddress((void**)&h1,    g_h1);
    cudaGetSymbolAddress((void**)&t,     g_t);
    cudaGetSymbolAddress((void**)&qkv,   g_qkv);
    cudaGetSymbolAddress((void**)&ctx,   g_ctx);
    cudaGetSymbolAddress((void**)&sc,    g_s);
    cudaGetSymbolAddress((void**)&p,     g_p);
    cudaGetSymbolAddress((void**)&mlp,   g_mlp);
    cudaGetSymbolAddress((void**)&wqkvh, g_wqkv);
    cudaGetSymbolAddress((void**)&bqkv,  g_bqkv);
    cudaGetSymbolAddress((void**)&wdh,   g_wd);
    cudaGetSymbolAddress((void**)&wmhh,  g_wmh);
    cudaGetSymbolAddress((void**)&wmoh,  g_wmo);

    // weight conversion — all contiguous fast path (no scatter)
    {
        const int n_qkv = LL * DD * DH / 4;   // float4 count per matrix family
        const int n_mlp = LL * DD * HID / 4;
        const long long wsz = (long long)LL * DD * DH;   // halves per family
        f2h_kernel<<<(n_qkv + 511) / 512, 256>>>((const float4*)wq_w, (__half2*)(wqkvh),           n_qkv);
        f2h_kernel<<<(n_qkv + 511) / 512, 256>>>((const float4*)wk_w, (__half2*)(wqkvh + wsz),     n_qkv);
        f2h_kernel<<<(n_qkv + 511) / 512, 256>>>((const float4*)wv_w, (__half2*)(wqkvh + 2 * wsz), n_qkv);
        bias_copy3<<<(LL * DH + 255) / 256, 256>>>(wq_b, wk_b, wv_b, bqkv);
        f2h_kernel<<<(n_qkv + 511) / 512, 256>>>((const float4*)dn_w, (__half2*)wdh,  n_qkv);
        f2h_kernel<<<(n_mlp + 511) / 512, 256>>>((const float4*)mh_w, (__half2*)wmhh, n_mlp);
        f2h_kernel<<<(n_mlp + 511) / 512, 256>>>((const float4*)mo_w, (__half2*)wmoh, n_mlp);
    }

    const float inv_sqrt_d = 0.044194173824159216f;
    const long long QKV_PLANE = (long long)MTOK * DH;    // output plane stride
    const long long W_FAM     = (long long)LL * DD * DH; // weight family stride

    embed_kernel<<<(MTOK * DD + 255) / 256, 256>>>(x, in_w, in_b, h);

    for (int i = 0; i < LL; i++) {
        // batched QKV: z in {Q,K,V}; [10752,512] @ [512,4096] per z (128x128 tile)
        run_gemm<128,128,4,2,2, 0, false,true,false,true>(
            h, wqkvh + (long long)i * DD * DH, bqkv + (long long)i * DH, nullptr, qkv,
            MTOK, DH, DD, DD, DH, DH,
            0, 0,                      // A: same for all z
            0, W_FAM,                  // B: per-z weight family
            0, QKV_PLANE,              // C: per-z output plane
            (long long)LL * DH,        // bias: per-z family stride
            3, 3, 1.0f);

        const __half* Q = qkv;
        const __half* K = qkv + QKV_PLANE;
        const __half* V = qkv + 2 * QKV_PLANE;

        // scores = Q @ K^T * inv_sqrt_d (64x64 tile, TRB, fp32 out, causal tile-skip)
        run_gemm<64,64,2,2,4, 1, true,false,false,false>(
            Q, K, nullptr, sc, nullptr,
            SS, SS, DD, DH, DH, SS,
            (long long)SS * DH, DD,
            (long long)SS * DH, DD,
            (long long)HH * SS * SS, (long long)SS * SS, 0,
            HH, BB * HH, inv_sqrt_d);

        softmax_kernel<<<(BB * HH * SS + 7) / 8, 256>>>(sc, p);

        // context = P @ V (64x128 tile, K-truncation)
        run_gemm<64,128,2,2,4, 2, false,false,false,true>(
            p, V, nullptr, nullptr, ctx,
            SS, DD, SS, SS, DH, DH,
            (long long)HH * SS * SS, (long long)SS * SS,
            (long long)SS * DH, DD,
            (long long)SS * DH, DD, 0,
            HH, BB * HH, 1.0f);

        // dn (64x128 tile: ratio 1.33, better waves; fp32 out -> LN)
        run_gemm<64,128,2,2,4, 0, false,true,false,false>(
            ctx, wdh + (long long)i * DH * DD, dn_b + (long long)i * DD, t, nullptr,
            MTOK, DD, DH, DH, DD, DD, 0,0,0,0,0,0,0, 1, 1, 1.0f);

        add_ln_kernel<<<MTOK, 256>>>(t, h, ln1g + (long long)i * DD, ln1b + (long long)i * DD, h1);

        // MLP up (big tile 128x128, relu, half out)
        run_gemm<128,128,4,2,2, 0, false,true,true,true>(
            h1, wmhh + (long long)i * DD * HID, mh_b + (long long)i * HID, nullptr, mlp,
            MTOK, HID, DD, DD, HID, HID, 0,0,0,0,0,0,0, 1, 1, 1.0f);

        // MLP down (64x128 tile; fp32 out -> LN)
        run_gemm<64,128,2,2,4, 0, false,true,false,false>(
            mlp, wmoh + (long long)i * HID * DD, mo_b + (long long)i * DD, t, nullptr,
            MTOK, DD, HID, HID, DD, DD, 0,0,0,0,0,0,0, 1, 1, 1.0f);

        add_ln_kernel<<<MTOK, 256>>>(t, h1, ln3g + (long long)i * DD, ln3b + (long long)i * DD, h);
    }

    out_kernel<<<(BB * NFUT + 3) / 4, 128>>>(h, ow, ob, (float*)d_out);
}